// round 13
// baseline (speedup 1.0000x reference)
#include <cuda_runtime.h>
#include <cuda_bf16.h>
#include <cuda_fp16.h>
#include <cstdint>

#define LSEQ 2048
#define DMODEL 2048
#define NH 16
#define DH 128
#define BATCH 2
#define MTOK (BATCH * LSEQ)                 // 4096
#define ACT_ELEMS ((size_t)MTOK * DMODEL)   // 8388608
#define W_ELEMS ((size_t)DMODEL * DMODEL)   // 4194304

// ---------------- scratch (static device arrays; no allocs) ----------------
__device__ __nv_bfloat16 g_sq[2 * ACT_ELEMS];
__device__ __nv_bfloat16 g_sk[2 * ACT_ELEMS];
__device__ __half        g_sv[ACT_ELEMS];
__device__ __half        g_sa[ACT_ELEMS];
__device__ __nv_bfloat16 g_qh2[2 * ACT_ELEMS];
__device__ __nv_bfloat16 g_kh2[2 * ACT_ELEMS];
__device__ __half        g_vh2[ACT_ELEMS];
__device__ __nv_bfloat16 g_swq[2 * W_ELEMS];
__device__ __nv_bfloat16 g_swk[2 * W_ELEMS];
__device__ __half        g_swv[W_ELEMS];
__device__ __half        g_swo[W_ELEMS];

// ---------------------------- PTX helpers ----------------------------------
__device__ __forceinline__ uint32_t smem_u32(const void* p) {
    uint32_t a;
    asm("{ .reg .u64 t; cvta.to.shared.u64 t, %1; cvt.u32.u64 %0, t; }"
        : "=r"(a) : "l"(p));
    return a;
}

__device__ __forceinline__ void cp16(uint32_t saddr, const void* g) {
    asm volatile("cp.async.cg.shared.global [%0], [%1], 16;"
                 :: "r"(saddr), "l"(g) : "memory");
}
#define CP_COMMIT() asm volatile("cp.async.commit_group;" ::: "memory")
#define CP_WAIT(n)  asm volatile("cp.async.wait_group %0;" :: "n"(n) : "memory")

__device__ __forceinline__ void ldsm_x4(uint32_t* r, uint32_t a) {
    asm volatile("ldmatrix.sync.aligned.m8n8.x4.shared.b16 {%0,%1,%2,%3}, [%4];"
                 : "=r"(r[0]), "=r"(r[1]), "=r"(r[2]), "=r"(r[3]) : "r"(a));
}
__device__ __forceinline__ void ldsm_x4t(uint32_t* r, uint32_t a) {
    asm volatile("ldmatrix.sync.aligned.m8n8.x4.trans.shared.b16 {%0,%1,%2,%3}, [%4];"
                 : "=r"(r[0]), "=r"(r[1]), "=r"(r[2]), "=r"(r[3]) : "r"(a));
}
__device__ __forceinline__ void mma_bf16(float* d, const uint32_t* a,
                                         const uint32_t* b) {
    asm volatile(
        "mma.sync.aligned.m16n8k16.row.col.f32.bf16.bf16.f32 "
        "{%0,%1,%2,%3}, {%4,%5,%6,%7}, {%8,%9}, {%0,%1,%2,%3};"
        : "+f"(d[0]), "+f"(d[1]), "+f"(d[2]), "+f"(d[3])
        : "r"(a[0]), "r"(a[1]), "r"(a[2]), "r"(a[3]), "r"(b[0]), "r"(b[1]));
}
__device__ __forceinline__ void mma_f16(float* d, const uint32_t* a,
                                        const uint32_t* b) {
    asm volatile(
        "mma.sync.aligned.m16n8k16.row.col.f32.f16.f16.f32 "
        "{%0,%1,%2,%3}, {%4,%5,%6,%7}, {%8,%9}, {%0,%1,%2,%3};"
        : "+f"(d[0]), "+f"(d[1]), "+f"(d[2]), "+f"(d[3])
        : "r"(a[0]), "r"(a[1]), "r"(a[2]), "r"(a[3]), "r"(b[0]), "r"(b[1]));
}

__device__ __forceinline__ void split2(float x, float y,
                                       uint32_t& hi, uint32_t& lo) {
    __nv_bfloat16 hx = __float2bfloat16(x);
    __nv_bfloat16 hy = __float2bfloat16(y);
    __nv_bfloat162 h2; h2.x = hx; h2.y = hy;
    hi = *reinterpret_cast<uint32_t*>(&h2);
    __nv_bfloat162 l2;
    l2.x = __float2bfloat16(x - __bfloat162float(hx));
    l2.y = __float2bfloat16(y - __bfloat162float(hy));
    lo = *reinterpret_cast<uint32_t*>(&l2);
}
__device__ __forceinline__ uint32_t pack2h(float x, float y) {
    __half2 h2 = __floats2half2_rn(x, y);
    return *reinterpret_cast<uint32_t*>(&h2);
}

__device__ __forceinline__ uint32_t sw256(int r, int q) {
    return (uint32_t)(r * 256 + ((q ^ (r & 7)) << 4));
}

// ---------------------------------------------------------------------------
// prep: 4 float4 per thread (MLP 4)
// ---------------------------------------------------------------------------
struct PrepArgs {
    const float* src[7];
    void* dst[7];
    int n4[7];
    int n[7];
    int type[7];
};

__device__ __forceinline__ void prep_one(const PrepArgs& a, int z, int i) {
    const float4 v = ((const float4*)a.src[z])[i];
    const int n = a.n[z];
    if (a.type[z] == 0) {
        uint32_t h0, l0, h1, l1;
        split2(v.x, v.y, h0, l0);
        split2(v.z, v.w, h1, l1);
        uint32_t* hp = (uint32_t*)a.dst[z];
        uint32_t* lp = (uint32_t*)((__nv_bfloat16*)a.dst[z] + n);
        hp[2 * i] = h0; hp[2 * i + 1] = h1;
        lp[2 * i] = l0; lp[2 * i + 1] = l1;
    } else {
        uint32_t* hp = (uint32_t*)a.dst[z];
        hp[2 * i]     = pack2h(v.x, v.y);
        hp[2 * i + 1] = pack2h(v.z, v.w);
    }
}

__global__ __launch_bounds__(256)
void prep(PrepArgs a)
{
    const int z = blockIdx.z;
    const int quarter = a.n4[z] >> 2;
    const int i = blockIdx.x * 256 + threadIdx.x;
    if (i >= quarter) return;
    prep_one(a, z, i);
    prep_one(a, z, i + quarter);
    prep_one(a, z, i + 2 * quarter);
    prep_one(a, z, i + 3 * quarter);
}

// ---------------------------------------------------------------------------
// GEMM geometry — round-9 config (128x128 tile, 256 thr, 2 CTA/SM)
// ---------------------------------------------------------------------------
#define TILE_B   8192
#define NSTAGE   3
#define NCHUNK   (DMODEL / 32)
#define STAGE4_B (4 * TILE_B)
#define GS4_B    (NSTAGE * STAGE4_B)   // 96 KB

#define TILEH_B  16384
#define STAGEH_B (2 * TILEH_B)
#define GSH_B    (NSTAGE * STAGEH_B)   // 96 KB
#define NCHUNK64 (DMODEL / 64)

__device__ __forceinline__ void mainloop_bf3(
    const __nv_bfloat16* Ahi, const __nv_bfloat16* Alo,
    const __nv_bfloat16* Bhi, const __nv_bfloat16* Blo,
    int bm, int bn, uint32_t sbase, float acc[4][4][4])
{
    const int tid = threadIdx.x;
    const int lane = tid & 31;
    const int wid = tid >> 5;
    const int wm = wid & 1;
    const int wn = wid >> 1;
    const int r = tid >> 2;
    const int q = tid & 3;

    auto load_stage = [&](int kc, int s) {
        const int k0 = kc * 32;
        const uint32_t st = sbase + (uint32_t)s * STAGE4_B;
        const __nv_bfloat16* srcs[4] = {Ahi, Alo, Bhi, Blo};
        const int row0[4] = {bm, bm, bn, bn};
#pragma unroll
        for (int t = 0; t < 4; t++) {
            const __nv_bfloat16* g0 =
                srcs[t] + (size_t)(row0[t] + r) * DMODEL + k0 + q * 8;
#pragma unroll
            for (int half = 0; half < 2; half++) {
                const int rr = r + half * 64;
                const uint32_t soff = (uint32_t)t * TILE_B + rr * 64 +
                                      ((q ^ ((rr >> 1) & 3)) * 16);
                cp16(st + soff, g0 + (size_t)half * 64 * DMODEL);
            }
        }
    };

    load_stage(0, 0); CP_COMMIT();
    load_stage(1, 1); CP_COMMIT();

    for (int kc = 0; kc < NCHUNK; kc++) {
        const int s = kc % NSTAGE;
        CP_WAIT(1);
        __syncthreads();
        if (kc + 2 < NCHUNK) load_stage(kc + 2, (kc + 2) % NSTAGE);
        CP_COMMIT();

        const uint32_t st = sbase + (uint32_t)s * STAGE4_B;
        const uint32_t sAh = st;
        const uint32_t sAl = st + TILE_B;
        const uint32_t sBh = st + 2 * TILE_B;
        const uint32_t sBl = st + 3 * TILE_B;

#pragma unroll
        for (int ks = 0; ks < 2; ks++) {
            uint32_t ah[4][4], al[4][4], bh4[2][4], bl4[2][4];
#pragma unroll
            for (int mt = 0; mt < 4; mt++) {
                const int row = wm * 64 + mt * 16 + (lane & 15);
                const int kseg = ks * 2 + (lane >> 4);
                const uint32_t off =
                    row * 64 + ((kseg ^ ((row >> 1) & 3)) * 16);
                ldsm_x4(ah[mt], sAh + off);
                ldsm_x4(al[mt], sAl + off);
            }
#pragma unroll
            for (int p = 0; p < 2; p++) {
                const int nrow = wn * 32 + p * 16 + ((lane >> 4) & 1) * 8 +
                                 (lane & 7);
                const int kseg = ks * 2 + ((lane >> 3) & 1);
                const uint32_t off =
                    nrow * 64 + ((kseg ^ ((nrow >> 1) & 3)) * 16);
                ldsm_x4(bh4[p], sBh + off);
                ldsm_x4(bl4[p], sBl + off);
            }
#pragma unroll
            for (int mt = 0; mt < 4; mt++)
#pragma unroll
                for (int nt = 0; nt < 4; nt++) {
                    const uint32_t* bh = &bh4[nt >> 1][(nt & 1) * 2];
                    const uint32_t* bl = &bl4[nt >> 1][(nt & 1) * 2];
                    mma_bf16(acc[mt][nt], ah[mt], bh);
                    mma_bf16(acc[mt][nt], ah[mt], bl);
                    mma_bf16(acc[mt][nt], al[mt], bh);
                }
        }
    }
}

__device__ __forceinline__ void mainloop_h1(
    const __half* A, const __half* B,
    int bm, int bn, uint32_t sbase, float acc[4][4][4])
{
    const int tid = threadIdx.x;
    const int lane = tid & 31;
    const int wid = tid >> 5;
    const int wm = wid & 1;
    const int wn = wid >> 1;

    auto load_stage = [&](int kc, int s) {
        const int k0 = kc * 64;
        const uint32_t st = sbase + (uint32_t)s * STAGEH_B;
#pragma unroll
        for (int j = 0; j < 8; j++) {
            const int c = tid + 256 * j;
            const int t = c >> 10;
            const int u = c & 1023;
            const int r = u >> 3;
            const int q = u & 7;
            const __half* g = (t ? B + (size_t)(bn + r) * DMODEL
                                 : A + (size_t)(bm + r) * DMODEL) + k0 + q * 8;
            cp16(st + (uint32_t)t * TILEH_B + r * 128 +
                 (((q ^ (r & 7)) << 4)), g);
        }
    };

    load_stage(0, 0); CP_COMMIT();
    load_stage(1, 1); CP_COMMIT();

    for (int kc = 0; kc < NCHUNK64; kc++) {
        const int s = kc % NSTAGE;
        CP_WAIT(1);
        __syncthreads();
        if (kc + 2 < NCHUNK64) load_stage(kc + 2, (kc + 2) % NSTAGE);
        CP_COMMIT();

        const uint32_t sA = sbase + (uint32_t)s * STAGEH_B;
        const uint32_t sB = sA + TILEH_B;

#pragma unroll
        for (int ks = 0; ks < 4; ks++) {
            uint32_t ah[4][4], b4[2][4];
#pragma unroll
            for (int mt = 0; mt < 4; mt++) {
                const int row = wm * 64 + mt * 16 + (lane & 15);
                const int kseg = ks * 2 + (lane >> 4);
                ldsm_x4(ah[mt], sA + row * 128 + ((kseg ^ (row & 7)) << 4));
            }
#pragma unroll
            for (int p = 0; p < 2; p++) {
                const int nrow = wn * 32 + p * 16 + ((lane >> 4) & 1) * 8 +
                                 (lane & 7);
                const int kseg = ks * 2 + ((lane >> 3) & 1);
                ldsm_x4(b4[p], sB + nrow * 128 + ((kseg ^ (nrow & 7)) << 4));
            }
#pragma unroll
            for (int mt = 0; mt < 4; mt++)
#pragma unroll
                for (int nt = 0; nt < 4; nt++)
                    mma_f16(acc[mt][nt], ah[mt], &b4[nt >> 1][(nt & 1) * 2]);
        }
    }
}

// ---------------------------------------------------------------------------
// Fused Q/K/V projection GEMM — round-9 launch (grid 16x32x3)
// ---------------------------------------------------------------------------
struct QKVArgs {
    const __nv_bfloat16* Ah[2];
    const __nv_bfloat16* Al[2];
    const __nv_bfloat16* Bh[2];
    const __nv_bfloat16* Bl[2];
    const float* bias[2];
    __nv_bfloat16* Ch[2];
    __nv_bfloat16* Cl[2];
    const __half* vA;
    const __half* vB;
    const float* vbias;
    __half* vC;
};

__global__ __launch_bounds__(256)
void gemm_qkv(QKVArgs args)
{
    extern __shared__ char smb[];
    const uint32_t sbase = smem_u32(smb);
    const int sel = blockIdx.z;
    const int bn = blockIdx.x * 128;
    const int bm = blockIdx.y * 128;
    const int lane = threadIdx.x & 31;
    const int wid = threadIdx.x >> 5;
    const int wm = wid & 1;
    const int wn = wid >> 1;

    float acc[4][4][4];
#pragma unroll
    for (int i = 0; i < 4; i++)
#pragma unroll
        for (int j = 0; j < 4; j++)
#pragma unroll
            for (int c = 0; c < 4; c++) acc[i][j][c] = 0.f;

    if (sel < 2) {
        mainloop_bf3(args.Ah[sel], args.Al[sel], args.Bh[sel], args.Bl[sel],
                     bm, bn, sbase, acc);
        const float* bias = args.bias[sel];
        __nv_bfloat16* Ch = args.Ch[sel];
        __nv_bfloat16* Cl = args.Cl[sel];
#pragma unroll
        for (int mt = 0; mt < 4; mt++) {
#pragma unroll
            for (int nt = 0; nt < 4; nt++) {
                const int m0 = bm + wm * 64 + mt * 16 + (lane >> 2);
                const int n0 = bn + wn * 32 + nt * 8 + (lane & 3) * 2;
                const float bia0 = __ldg(&bias[n0]);
                const float bia1 = __ldg(&bias[n0 + 1]);
#pragma unroll
                for (int half = 0; half < 2; half++) {
                    const int m = m0 + half * 8;
                    const float x0 = acc[mt][nt][half * 2] + bia0;
                    const float x1 = acc[mt][nt][half * 2 + 1] + bia1;
                    const int h = bn >> 7;
                    const int b = m >> 11;
                    const int l = m & (LSEQ - 1);
                    const size_t idx =
                        (((size_t)(b * NH + h) * LSEQ + l) * DH) + (n0 & 127);
                    uint32_t hi, lo;
                    split2(x0, x1, hi, lo);
                    *(uint32_t*)(Ch + idx) = hi;
                    *(uint32_t*)(Cl + idx) = lo;
                }
            }
        }
    } else {
        mainloop_h1(args.vA, args.vB, bm, bn, sbase, acc);
        const float* bias = args.vbias;
        __half* C = args.vC;
#pragma unroll
        for (int mt = 0; mt < 4; mt++) {
#pragma unroll
            for (int nt = 0; nt < 4; nt++) {
                const int m0 = bm + wm * 64 + mt * 16 + (lane >> 2);
                const int n0 = bn + wn * 32 + nt * 8 + (lane & 3) * 2;
                const float bia0 = __ldg(&bias[n0]);
                const float bia1 = __ldg(&bias[n0 + 1]);
#pragma unroll
                for (int half = 0; half < 2; half++) {
                    const int m = m0 + half * 8;
                    const int h = bn >> 7;
                    const int b = m >> 11;
                    const int l = m & (LSEQ - 1);
                    const size_t idx =
                        (((size_t)(b * NH + h) * LSEQ + l) * DH) + (n0 & 127);
                    *(uint32_t*)(C + idx) =
                        pack2h(acc[mt][nt][half * 2] + bia0,
                               acc[mt][nt][half * 2 + 1] + bia1);
                }
            }
        }
    }
}

// ---------------------------------------------------------------------------
// Output projection (round-9 config)
// ---------------------------------------------------------------------------
__global__ __launch_bounds__(256)
void gemm_wo(const __half* __restrict__ A, const __half* __restrict__ B,
             const float* __restrict__ bias, float* __restrict__ C)
{
    extern __shared__ char smb[];
    const uint32_t sbase = smem_u32(smb);
    const int bn = blockIdx.x * 128;
    const int bm = blockIdx.y * 128;
    const int lane = threadIdx.x & 31;
    const int wid = threadIdx.x >> 5;
    const int wm = wid & 1;
    const int wn = wid >> 1;

    float acc[4][4][4];
#pragma unroll
    for (int i = 0; i < 4; i++)
#pragma unroll
        for (int j = 0; j < 4; j++)
#pragma unroll
            for (int c = 0; c < 4; c++) acc[i][j][c] = 0.f;

    mainloop_h1(A, B, bm, bn, sbase, acc);

#pragma unroll
    for (int mt = 0; mt < 4; mt++) {
#pragma unroll
        for (int nt = 0; nt < 4; nt++) {
            const int m0 = bm + wm * 64 + mt * 16 + (lane >> 2);
            const int n0 = bn + wn * 32 + nt * 8 + (lane & 3) * 2;
            const float bia0 = __ldg(&bias[n0]);
            const float bia1 = __ldg(&bias[n0 + 1]);
#pragma unroll
            for (int half = 0; half < 2; half++) {
                const int m = m0 + half * 8;
                *(float2*)(C + (size_t)m * DMODEL + n0) =
                    make_float2(acc[mt][nt][half * 2] + bia0,
                                acc[mt][nt][half * 2 + 1] + bia1);
            }
        }
    }
}

// ---------------------------------------------------------------------------
// Flash attention — round-9 geometry + causal work-skipping (bit-identical):
//  - warps skip k-tiles entirely above their diagonal
//  - within diagonal tiles, skip fully-masked 8-col n-subtiles and PV k-steps
// ---------------------------------------------------------------------------
#define NQT (LSEQ / 128)
#define FST_B (3 * 64 * 256)                     // 48 KB
#define FQ_B  (2 * 128 * 256)                    // 64 KB
#define FSMEM_B (FQ_B + 3 * FST_B)               // 208 KB
#define FSCALE 11.31370849898476f

__global__ __launch_bounds__(256, 1)
void flash_mma(const __nv_bfloat16* __restrict__ Qhi,
               const __nv_bfloat16* __restrict__ Qlo,
               const __nv_bfloat16* __restrict__ Khi,
               const __nv_bfloat16* __restrict__ Klo,
               const __half* __restrict__ V,
               __half* __restrict__ O)
{
    extern __shared__ char smb[];
    const uint32_t sbase = smem_u32(smb);
    const uint32_t qlo_s = sbase + 128 * 256;
    const uint32_t stage0 = sbase + FQ_B;

    const int tid = threadIdx.x;
    const int lane = tid & 31;
    const int w = tid >> 5;

    const int bx = blockIdx.x;
    const int qt = (NQT - 1) - (bx >> 5);
    const int hb = bx & 31;
    const int h = hb & 15;
    const int b = hb >> 4;
    const int bh = b * NH + h;
    const int NKT = 2 * (qt + 1);

    const __nv_bfloat16* qh_g = Qhi + (size_t)bh * LSEQ * DH;
    const __nv_bfloat16* ql_g = Qlo + (size_t)bh * LSEQ * DH;
    const __nv_bfloat16* kh_g = Khi + (size_t)bh * LSEQ * DH;
    const __nv_bfloat16* kl_g = Klo + (size_t)bh * LSEQ * DH;
    const __half*        v_g  = V   + (size_t)bh * LSEQ * DH;

    {
#pragma unroll
        for (int j = 0; j < 16; j++) {
            const int c = tid + 256 * j;
            const int t = c >> 11;
            const int u = c & 2047;
            const int r = u >> 4;
            const int q = u & 15;
            const __nv_bfloat16* src = (t ? ql_g : qh_g) +
                (size_t)(qt * 128 + r) * DH + q * 8;
            cp16(sbase + (uint32_t)t * (128 * 256) + sw256(r, q), src);
        }
        CP_COMMIT();
    }

    auto load_stage = [&](int kt, int s) {
        const uint32_t st = stage0 + (uint32_t)s * FST_B;
#pragma unroll
        for (int j = 0; j < 12; j++) {
            const int c = tid + 256 * j;
            const int t = c >> 10;
            const int u = c & 1023;
            const int r = u >> 4;
            const int q = u & 15;
            const char* src =
                (t == 0 ? (const char*)kh_g :
                 t == 1 ? (const char*)kl_g : (const char*)v_g) +
                ((size_t)(kt * 64 + r) * DH + q * 8) * 2;
            cp16(st + (uint32_t)t * 16384 + sw256(r, q), src);
        }
        CP_COMMIT();
    };

    load_stage(0, 0);
    load_stage(1, 1);

    CP_WAIT(2);
    __syncthreads();

    uint32_t qfh[8][4];
#pragma unroll
    for (int ks = 0; ks < 8; ks++) {
        const int row = w * 16 + (lane & 15);
        const int q = ks * 2 + (lane >> 4);
        ldsm_x4(qfh[ks], sbase + sw256(row, q));
    }

    float O_acc[16][4];
#pragma unroll
    for (int nd = 0; nd < 16; nd++)
#pragma unroll
        for (int c = 0; c < 4; c++) O_acc[nd][c] = 0.f;
    float m0 = -3.0e38f, m1 = -3.0e38f, l0 = 0.f, l1 = 0.f;

    const int iq0 = qt * 128 + w * 16 + (lane >> 2);
    const int jcol = (lane & 3) * 2;
    const int rowmax = qt * 128 + w * 16 + 15;   // last row of this warp

    for (int kt = 0; kt < NKT; kt++) {
        if (kt + 1 < NKT) { CP_WAIT(1); } else { CP_WAIT(0); }
        __syncthreads();
        if (kt + 2 < NKT) load_stage(kt + 2, (kt + 2) % 3);

        const int colbase = kt * 64;
        if (colbase > rowmax) continue;   // tile fully above diagonal: exact no-op

        const uint32_t st = stage0 + (uint32_t)(kt % 3) * FST_B;
        const uint32_t sKh = st;
        const uint32_t sKl = st + 16384;
        const uint32_t sV  = st + 32768;

        float S[8][4];
#pragma unroll
        for (int nt = 0; nt < 8; nt++)
#pragma unroll
            for (int c = 0; c < 4; c++) S[nt][c] = 0.f;

#pragma unroll
        for (int ks = 0; ks < 8; ks++) {
            uint32_t ql[4];
            {
                const int row = w * 16 + (lane & 15);
                const int q = ks * 2 + (lane >> 4);
                ldsm_x4(ql, qlo_s + sw256(row, q));
            }
            uint32_t kh4[4][4], kl4[4][4];
#pragma unroll
            for (int p = 0; p < 4; p++) {
                if (colbase + p * 16 > rowmax) continue;  // both nts masked
                const int row = p * 16 + ((lane >> 4) & 1) * 8 + (lane & 7);
                const int q = ks * 2 + ((lane >> 3) & 1);
                ldsm_x4(kh4[p], sKh + sw256(row, q));
                ldsm_x4(kl4[p], sKl + sw256(row, q));
            }
#pragma unroll
            for (int nt = 0; nt < 8; nt++) {
                if (colbase + nt * 8 > rowmax) continue;  // masked subtile
                const uint32_t* kh = &kh4[nt >> 1][(nt & 1) * 2];
                const uint32_t* kl = &kl4[nt >> 1][(nt & 1) * 2];
                mma_bf16(S[nt], qfh[ks], kh);
                mma_bf16(S[nt], qfh[ks], kl);
                mma_bf16(S[nt], ql, kh);
            }
        }

        const bool tilemask = (colbase + 63) > (qt * 128 + w * 16);
#pragma unroll
        for (int nt = 0; nt < 8; nt++) {
#pragma unroll
            for (int c = 0; c < 4; c++) {
                float s = S[nt][c] * FSCALE;
                if (tilemask) {
                    const int i = iq0 + ((c & 2) ? 8 : 0);
                    const int j = colbase + nt * 8 + jcol + (c & 1);
                    if (j > i) s -= 1e7f;
                }
                S[nt][c] = s;
            }
        }

        float tm0 = -3.0e38f, tm1 = -3.0e38f;
#pragma unroll
        for (int nt = 0; nt < 8; nt++) {
            tm0 = fmaxf(tm0, fmaxf(S[nt][0], S[nt][1]));
            tm1 = fmaxf(tm1, fmaxf(S[nt][2], S[nt][3]));
        }
        tm0 = fmaxf(tm0, __shfl_xor_sync(0xffffffffu, tm0, 1));
        tm0 = fmaxf(tm0, __shfl_xor_sync(0xffffffffu, tm0, 2));
        tm1 = fmaxf(tm1, __shfl_xor_sync(0xffffffffu, tm1, 1));
        tm1 = fmaxf(tm1, __shfl_xor_sync(0xffffffffu, tm1, 2));
        const float nm0 = fmaxf(m0, tm0);
        const float nm1 = fmaxf(m1, tm1);

        const unsigned skip =
            __all_sync(0xffffffffu, (nm0 == m0) && (nm1 == m1));
        if (!skip) {
            const float a0 = __expf(m0 - nm0);
            const float a1 = __expf(m1 - nm1);
            l0 *= a0; l1 *= a1;
#pragma unroll
            for (int nd = 0; nd < 16; nd++) {
                O_acc[nd][0] *= a0; O_acc[nd][1] *= a0;
                O_acc[nd][2] *= a1; O_acc[nd][3] *= a1;
            }
            m0 = nm0; m1 = nm1;
        }

        float s0 = 0.f, s1 = 0.f;
#pragma unroll
        for (int nt = 0; nt < 8; nt++) {
            S[nt][0] = __half2float(__float2half_rn(__expf(S[nt][0] - m0)));
            S[nt][1] = __half2float(__float2half_rn(__expf(S[nt][1] - m0)));
            S[nt][2] = __half2float(__float2half_rn(__expf(S[nt][2] - m1)));
            S[nt][3] = __half2float(__float2half_rn(__expf(S[nt][3] - m1)));
            s0 += S[nt][0] + S[nt][1];
            s1 += S[nt][2] + S[nt][3];
        }
        s0 += __shfl_xor_sync(0xffffffffu, s0, 1);
        s0 += __shfl_xor_sync(0xffffffffu, s0, 2);
        s1 += __shfl_xor_sync(0xffffffffu, s1, 1);
        s1 += __shfl_xor_sync(0xffffffffu, s1, 2);
        l0 += s0;
        l1 += s1;

#pragma unroll
        for (int ks2 = 0; ks2 < 4; ks2++) {
            if (colbase + ks2 * 16 > rowmax) continue;  // P block all zero
            const int nt0 = 2 * ks2, nt1 = nt0 + 1;
            uint32_t ph[4];
            ph[0] = pack2h(S[nt0][0], S[nt0][1]);
            ph[1] = pack2h(S[nt0][2], S[nt0][3]);
            ph[2] = pack2h(S[nt1][0], S[nt1][1]);
            ph[3] = pack2h(S[nt1][2], S[nt1][3]);
            const int vrow = ks2 * 16 + (lane & 15);
#pragma unroll
            for (int np = 0; np < 8; np++) {
                uint32_t vv[4];
                const int seg = np * 2 + (lane >> 4);
                ldsm_x4t(vv, sV + sw256(vrow, seg));
                mma_f16(O_acc[2 * np],     ph, vv);
                mma_f16(O_acc[2 * np + 1], ph, vv + 2);
            }
        }
    }

    const float inv0 = 1.0f / l0;
    const float inv1 = 1.0f / l1;
    const size_t tok0 = (size_t)b * LSEQ + qt * 128 + w * 16 + (lane >> 2);
    const size_t tok1 = tok0 + 8;
    const int col = h * DH + jcol;
#pragma unroll
    for (int nd = 0; nd < 16; nd++) {
        const int cc = col + nd * 8;
        *(uint32_t*)(O + tok0 * DMODEL + cc) =
            pack2h(O_acc[nd][0] * inv0, O_acc[nd][1] * inv0);
        *(uint32_t*)(O + tok1 * DMODEL + cc) =
            pack2h(O_acc[nd][2] * inv1, O_acc[nd][3] * inv1);
    }
}

// ---------------------------------------------------------------------------
extern "C" void kernel_launch(void* const* d_in, const int* in_sizes, int n_in,
                              void* d_out, int out_size)
{
    (void)in_sizes; (void)n_in; (void)out_size;
    const float* q  = (const float*)d_in[0];
    const float* k  = (const float*)d_in[1];
    const float* v  = (const float*)d_in[2];
    const float* Wq = (const float*)d_in[3];
    const float* bq = (const float*)d_in[4];
    const float* Wk = (const float*)d_in[5];
    const float* bk = (const float*)d_in[6];
    const float* Wv = (const float*)d_in[7];
    const float* bv = (const float*)d_in[8];
    const float* Wo = (const float*)d_in[9];
    const float* bo = (const float*)d_in[10];
    float* out = (float*)d_out;

    __nv_bfloat16 *sq, *sk, *qh2, *kh2, *swq, *swk;
    __half *sv, *sa, *vh2, *swv, *swo;
    cudaGetSymbolAddress((void**)&sq, g_sq);
    cudaGetSymbolAddress((void**)&sk, g_sk);
    cudaGetSymbolAddress((void**)&sv, g_sv);
    cudaGetSymbolAddress((void**)&sa, g_sa);
    cudaGetSymbolAddress((void**)&qh2, g_qh2);
    cudaGetSymbolAddress((void**)&kh2, g_kh2);
    cudaGetSymbolAddress((void**)&vh2, g_vh2);
    cudaGetSymbolAddress((void**)&swq, g_swq);
    cudaGetSymbolAddress((void**)&swk, g_swk);
    cudaGetSymbolAddress((void**)&swv, g_swv);
    cudaGetSymbolAddress((void**)&swo, g_swo);

    cudaFuncSetAttribute(gemm_qkv, cudaFuncAttributeMaxDynamicSharedMemorySize,
                         GS4_B);
    cudaFuncSetAttribute(gemm_wo, cudaFuncAttributeMaxDynamicSharedMemorySize,
                         GSH_B);
    cudaFuncSetAttribute(flash_mma, cudaFuncAttributeMaxDynamicSharedMemorySize,
                         FSMEM_B);

    // ---- prep (4 float4 per thread) ----
    PrepArgs pa;
    pa.src[0] = q;  pa.dst[0] = sq;  pa.n[0] = (int)ACT_ELEMS; pa.type[0] = 0;
    pa.src[1] = k;  pa.dst[1] = sk;  pa.n[1] = (int)ACT_ELEMS; pa.type[1] = 0;
    pa.src[2] = v;  pa.dst[2] = sv;  pa.n[2] = (int)ACT_ELEMS; pa.type[2] = 2;
    pa.src[3] = Wq; pa.dst[3] = swq; pa.n[3] = (int)W_ELEMS;   pa.type[3] = 0;
    pa.src[4] = Wk; pa.dst[4] = swk; pa.n[4] = (int)W_ELEMS;   pa.type[4] = 0;
    pa.src[5] = Wv; pa.dst[5] = swv; pa.n[5] = (int)W_ELEMS;   pa.type[5] = 2;
    pa.src[6] = Wo; pa.dst[6] = swo; pa.n[6] = (int)W_ELEMS;   pa.type[6] = 2;
    for (int i = 0; i < 7; i++) pa.n4[i] = pa.n[i] / 4;
    prep<<<dim3((int)(ACT_ELEMS / 16 / 256), 1, 7), 256>>>(pa);

    // ---- fused Q/K/V projections (round-9 launch) ----
    QKVArgs qa;
    qa.Ah[0] = sq;  qa.Al[0] = sq + ACT_ELEMS;
    qa.Ah[1] = sk;  qa.Al[1] = sk + ACT_ELEMS;
    qa.Bh[0] = swq; qa.Bl[0] = swq + W_ELEMS;
    qa.Bh[1] = swk; qa.Bl[1] = swk + W_ELEMS;
    qa.bias[0] = bq; qa.bias[1] = bk;
    qa.Ch[0] = qh2; qa.Cl[0] = qh2 + ACT_ELEMS;
    qa.Ch[1] = kh2; qa.Cl[1] = kh2 + ACT_ELEMS;
    qa.vA = sv; qa.vB = swv; qa.vbias = bv; qa.vC = vh2;
    gemm_qkv<<<dim3(DMODEL / 128, MTOK / 128, 3), 256, GS4_B>>>(qa);

    // ---- attention (round-9 flash + causal skipping) ----
    flash_mma<<<NQT * NH * BATCH, 256, FSMEM_B>>>(
        qh2, qh2 + ACT_ELEMS, kh2, kh2 + ACT_ELEMS, vh2, sa);

    // ---- output projection ----
    gemm_wo<<<dim3(DMODEL / 128, MTOK / 128), 256, GSH_B>>>(sa, swo, bo, out);
}

// round 14
// speedup vs baseline: 1.0345x; 1.0345x over previous
#include <cuda_runtime.h>
#include <cuda_bf16.h>
#include <cuda_fp16.h>
#include <cstdint>

#define LSEQ 2048
#define DMODEL 2048
#define NH 16
#define DH 128
#define BATCH 2
#define MTOK (BATCH * LSEQ)                 // 4096
#define ACT_ELEMS ((size_t)MTOK * DMODEL)   // 8388608
#define W_ELEMS ((size_t)DMODEL * DMODEL)   // 4194304

// ---------------- scratch (static device arrays; no allocs) ----------------
__device__ __nv_bfloat16 g_sq[2 * ACT_ELEMS];
__device__ __nv_bfloat16 g_sk[2 * ACT_ELEMS];
__device__ __half        g_sv[ACT_ELEMS];
__device__ __half        g_sa[ACT_ELEMS];
__device__ __nv_bfloat16 g_qh2[2 * ACT_ELEMS];
__device__ __nv_bfloat16 g_kh2[2 * ACT_ELEMS];
__device__ __half        g_vh2[ACT_ELEMS];
__device__ __nv_bfloat16 g_swq[2 * W_ELEMS];
__device__ __nv_bfloat16 g_swk[2 * W_ELEMS];
__device__ __half        g_swv[W_ELEMS];
__device__ __half        g_swo[W_ELEMS];

// ---------------------------- PTX helpers ----------------------------------
__device__ __forceinline__ uint32_t smem_u32(const void* p) {
    uint32_t a;
    asm("{ .reg .u64 t; cvta.to.shared.u64 t, %1; cvt.u32.u64 %0, t; }"
        : "=r"(a) : "l"(p));
    return a;
}

__device__ __forceinline__ void cp16(uint32_t saddr, const void* g) {
    asm volatile("cp.async.cg.shared.global [%0], [%1], 16;"
                 :: "r"(saddr), "l"(g) : "memory");
}
#define CP_COMMIT() asm volatile("cp.async.commit_group;" ::: "memory")
#define CP_WAIT(n)  asm volatile("cp.async.wait_group %0;" :: "n"(n) : "memory")

__device__ __forceinline__ void ldsm_x4(uint32_t* r, uint32_t a) {
    asm volatile("ldmatrix.sync.aligned.m8n8.x4.shared.b16 {%0,%1,%2,%3}, [%4];"
                 : "=r"(r[0]), "=r"(r[1]), "=r"(r[2]), "=r"(r[3]) : "r"(a));
}
__device__ __forceinline__ void ldsm_x4t(uint32_t* r, uint32_t a) {
    asm volatile("ldmatrix.sync.aligned.m8n8.x4.trans.shared.b16 {%0,%1,%2,%3}, [%4];"
                 : "=r"(r[0]), "=r"(r[1]), "=r"(r[2]), "=r"(r[3]) : "r"(a));
}
__device__ __forceinline__ void mma_bf16(float* d, const uint32_t* a,
                                         const uint32_t* b) {
    asm volatile(
        "mma.sync.aligned.m16n8k16.row.col.f32.bf16.bf16.f32 "
        "{%0,%1,%2,%3}, {%4,%5,%6,%7}, {%8,%9}, {%0,%1,%2,%3};"
        : "+f"(d[0]), "+f"(d[1]), "+f"(d[2]), "+f"(d[3])
        : "r"(a[0]), "r"(a[1]), "r"(a[2]), "r"(a[3]), "r"(b[0]), "r"(b[1]));
}
__device__ __forceinline__ void mma_f16(float* d, const uint32_t* a,
                                        const uint32_t* b) {
    asm volatile(
        "mma.sync.aligned.m16n8k16.row.col.f32.f16.f16.f32 "
        "{%0,%1,%2,%3}, {%4,%5,%6,%7}, {%8,%9}, {%0,%1,%2,%3};"
        : "+f"(d[0]), "+f"(d[1]), "+f"(d[2]), "+f"(d[3])
        : "r"(a[0]), "r"(a[1]), "r"(a[2]), "r"(a[3]), "r"(b[0]), "r"(b[1]));
}

__device__ __forceinline__ void split2(float x, float y,
                                       uint32_t& hi, uint32_t& lo) {
    __nv_bfloat16 hx = __float2bfloat16(x);
    __nv_bfloat16 hy = __float2bfloat16(y);
    __nv_bfloat162 h2; h2.x = hx; h2.y = hy;
    hi = *reinterpret_cast<uint32_t*>(&h2);
    __nv_bfloat162 l2;
    l2.x = __float2bfloat16(x - __bfloat162float(hx));
    l2.y = __float2bfloat16(y - __bfloat162float(hy));
    lo = *reinterpret_cast<uint32_t*>(&l2);
}
__device__ __forceinline__ uint32_t pack2h(float x, float y) {
    __half2 h2 = __floats2half2_rn(x, y);
    return *reinterpret_cast<uint32_t*>(&h2);
}

__device__ __forceinline__ uint32_t sw256(int r, int q) {
    return (uint32_t)(r * 256 + ((q ^ (r & 7)) << 4));
}

// ---------------------------------------------------------------------------
// prep — round-9 version (2 float4 per thread)
// ---------------------------------------------------------------------------
struct PrepArgs {
    const float* src[7];
    void* dst[7];
    int n4[7];
    int n[7];
    int type[7];
};

__device__ __forceinline__ void prep_one(const PrepArgs& a, int z, int i) {
    const float4 v = ((const float4*)a.src[z])[i];
    const int n = a.n[z];
    if (a.type[z] == 0) {
        uint32_t h0, l0, h1, l1;
        split2(v.x, v.y, h0, l0);
        split2(v.z, v.w, h1, l1);
        uint32_t* hp = (uint32_t*)a.dst[z];
        uint32_t* lp = (uint32_t*)((__nv_bfloat16*)a.dst[z] + n);
        hp[2 * i] = h0; hp[2 * i + 1] = h1;
        lp[2 * i] = l0; lp[2 * i + 1] = l1;
    } else {
        uint32_t* hp = (uint32_t*)a.dst[z];
        hp[2 * i]     = pack2h(v.x, v.y);
        hp[2 * i + 1] = pack2h(v.z, v.w);
    }
}

__global__ __launch_bounds__(256)
void prep(PrepArgs a)
{
    const int z = blockIdx.z;
    const int half = a.n4[z] >> 1;
    const int i = blockIdx.x * 256 + threadIdx.x;
    if (i >= half) return;
    prep_one(a, z, i);
    prep_one(a, z, i + half);
}

// ---------------------------------------------------------------------------
// GEMM geometry — round-9 config (128x128 tile, 256 thr, 2 CTA/SM)
// ---------------------------------------------------------------------------
#define TILE_B   8192
#define NSTAGE   3
#define NCHUNK   (DMODEL / 32)
#define STAGE4_B (4 * TILE_B)
#define GS4_B    (NSTAGE * STAGE4_B)   // 96 KB

#define TILEH_B  16384
#define STAGEH_B (2 * TILEH_B)
#define GSH_B    (NSTAGE * STAGEH_B)   // 96 KB
#define NCHUNK64 (DMODEL / 64)

__device__ __forceinline__ void mainloop_bf3(
    const __nv_bfloat16* Ahi, const __nv_bfloat16* Alo,
    const __nv_bfloat16* Bhi, const __nv_bfloat16* Blo,
    int bm, int bn, uint32_t sbase, float acc[4][4][4])
{
    const int tid = threadIdx.x;
    const int lane = tid & 31;
    const int wid = tid >> 5;
    const int wm = wid & 1;
    const int wn = wid >> 1;
    const int r = tid >> 2;
    const int q = tid & 3;

    auto load_stage = [&](int kc, int s) {
        const int k0 = kc * 32;
        const uint32_t st = sbase + (uint32_t)s * STAGE4_B;
        const __nv_bfloat16* srcs[4] = {Ahi, Alo, Bhi, Blo};
        const int row0[4] = {bm, bm, bn, bn};
#pragma unroll
        for (int t = 0; t < 4; t++) {
            const __nv_bfloat16* g0 =
                srcs[t] + (size_t)(row0[t] + r) * DMODEL + k0 + q * 8;
#pragma unroll
            for (int half = 0; half < 2; half++) {
                const int rr = r + half * 64;
                const uint32_t soff = (uint32_t)t * TILE_B + rr * 64 +
                                      ((q ^ ((rr >> 1) & 3)) * 16);
                cp16(st + soff, g0 + (size_t)half * 64 * DMODEL);
            }
        }
    };

    load_stage(0, 0); CP_COMMIT();
    load_stage(1, 1); CP_COMMIT();

    for (int kc = 0; kc < NCHUNK; kc++) {
        const int s = kc % NSTAGE;
        CP_WAIT(1);
        __syncthreads();
        if (kc + 2 < NCHUNK) load_stage(kc + 2, (kc + 2) % NSTAGE);
        CP_COMMIT();

        const uint32_t st = sbase + (uint32_t)s * STAGE4_B;
        const uint32_t sAh = st;
        const uint32_t sAl = st + TILE_B;
        const uint32_t sBh = st + 2 * TILE_B;
        const uint32_t sBl = st + 3 * TILE_B;

#pragma unroll
        for (int ks = 0; ks < 2; ks++) {
            uint32_t ah[4][4], al[4][4], bh4[2][4], bl4[2][4];
#pragma unroll
            for (int mt = 0; mt < 4; mt++) {
                const int row = wm * 64 + mt * 16 + (lane & 15);
                const int kseg = ks * 2 + (lane >> 4);
                const uint32_t off =
                    row * 64 + ((kseg ^ ((row >> 1) & 3)) * 16);
                ldsm_x4(ah[mt], sAh + off);
                ldsm_x4(al[mt], sAl + off);
            }
#pragma unroll
            for (int p = 0; p < 2; p++) {
                const int nrow = wn * 32 + p * 16 + ((lane >> 4) & 1) * 8 +
                                 (lane & 7);
                const int kseg = ks * 2 + ((lane >> 3) & 1);
                const uint32_t off =
                    nrow * 64 + ((kseg ^ ((nrow >> 1) & 3)) * 16);
                ldsm_x4(bh4[p], sBh + off);
                ldsm_x4(bl4[p], sBl + off);
            }
#pragma unroll
            for (int mt = 0; mt < 4; mt++)
#pragma unroll
                for (int nt = 0; nt < 4; nt++) {
                    const uint32_t* bh = &bh4[nt >> 1][(nt & 1) * 2];
                    const uint32_t* bl = &bl4[nt >> 1][(nt & 1) * 2];
                    mma_bf16(acc[mt][nt], ah[mt], bh);
                    mma_bf16(acc[mt][nt], ah[mt], bl);
                    mma_bf16(acc[mt][nt], al[mt], bh);
                }
        }
    }
}

__device__ __forceinline__ void mainloop_h1(
    const __half* A, const __half* B,
    int bm, int bn, uint32_t sbase, float acc[4][4][4])
{
    const int tid = threadIdx.x;
    const int lane = tid & 31;
    const int wid = tid >> 5;
    const int wm = wid & 1;
    const int wn = wid >> 1;

    auto load_stage = [&](int kc, int s) {
        const int k0 = kc * 64;
        const uint32_t st = sbase + (uint32_t)s * STAGEH_B;
#pragma unroll
        for (int j = 0; j < 8; j++) {
            const int c = tid + 256 * j;
            const int t = c >> 10;
            const int u = c & 1023;
            const int r = u >> 3;
            const int q = u & 7;
            const __half* g = (t ? B + (size_t)(bn + r) * DMODEL
                                 : A + (size_t)(bm + r) * DMODEL) + k0 + q * 8;
            cp16(st + (uint32_t)t * TILEH_B + r * 128 +
                 (((q ^ (r & 7)) << 4)), g);
        }
    };

    load_stage(0, 0); CP_COMMIT();
    load_stage(1, 1); CP_COMMIT();

    for (int kc = 0; kc < NCHUNK64; kc++) {
        const int s = kc % NSTAGE;
        CP_WAIT(1);
        __syncthreads();
        if (kc + 2 < NCHUNK64) load_stage(kc + 2, (kc + 2) % NSTAGE);
        CP_COMMIT();

        const uint32_t sA = sbase + (uint32_t)s * STAGEH_B;
        const uint32_t sB = sA + TILEH_B;

#pragma unroll
        for (int ks = 0; ks < 4; ks++) {
            uint32_t ah[4][4], b4[2][4];
#pragma unroll
            for (int mt = 0; mt < 4; mt++) {
                const int row = wm * 64 + mt * 16 + (lane & 15);
                const int kseg = ks * 2 + (lane >> 4);
                ldsm_x4(ah[mt], sA + row * 128 + ((kseg ^ (row & 7)) << 4));
            }
#pragma unroll
            for (int p = 0; p < 2; p++) {
                const int nrow = wn * 32 + p * 16 + ((lane >> 4) & 1) * 8 +
                                 (lane & 7);
                const int kseg = ks * 2 + ((lane >> 3) & 1);
                ldsm_x4(b4[p], sB + nrow * 128 + ((kseg ^ (nrow & 7)) << 4));
            }
#pragma unroll
            for (int mt = 0; mt < 4; mt++)
#pragma unroll
                for (int nt = 0; nt < 4; nt++)
                    mma_f16(acc[mt][nt], ah[mt], &b4[nt >> 1][(nt & 1) * 2]);
        }
    }
}

// ---------------------------------------------------------------------------
// Fused Q/K/V projection GEMM — round-9 launch (grid 16x32x3)
// ---------------------------------------------------------------------------
struct QKVArgs {
    const __nv_bfloat16* Ah[2];
    const __nv_bfloat16* Al[2];
    const __nv_bfloat16* Bh[2];
    const __nv_bfloat16* Bl[2];
    const float* bias[2];
    __nv_bfloat16* Ch[2];
    __nv_bfloat16* Cl[2];
    const __half* vA;
    const __half* vB;
    const float* vbias;
    __half* vC;
};

__global__ __launch_bounds__(256)
void gemm_qkv(QKVArgs args)
{
    extern __shared__ char smb[];
    const uint32_t sbase = smem_u32(smb);
    const int sel = blockIdx.z;
    const int bn = blockIdx.x * 128;
    const int bm = blockIdx.y * 128;
    const int lane = threadIdx.x & 31;
    const int wid = threadIdx.x >> 5;
    const int wm = wid & 1;
    const int wn = wid >> 1;

    float acc[4][4][4];
#pragma unroll
    for (int i = 0; i < 4; i++)
#pragma unroll
        for (int j = 0; j < 4; j++)
#pragma unroll
            for (int c = 0; c < 4; c++) acc[i][j][c] = 0.f;

    if (sel < 2) {
        mainloop_bf3(args.Ah[sel], args.Al[sel], args.Bh[sel], args.Bl[sel],
                     bm, bn, sbase, acc);
        const float* bias = args.bias[sel];
        __nv_bfloat16* Ch = args.Ch[sel];
        __nv_bfloat16* Cl = args.Cl[sel];
#pragma unroll
        for (int mt = 0; mt < 4; mt++) {
#pragma unroll
            for (int nt = 0; nt < 4; nt++) {
                const int m0 = bm + wm * 64 + mt * 16 + (lane >> 2);
                const int n0 = bn + wn * 32 + nt * 8 + (lane & 3) * 2;
                const float bia0 = __ldg(&bias[n0]);
                const float bia1 = __ldg(&bias[n0 + 1]);
#pragma unroll
                for (int half = 0; half < 2; half++) {
                    const int m = m0 + half * 8;
                    const float x0 = acc[mt][nt][half * 2] + bia0;
                    const float x1 = acc[mt][nt][half * 2 + 1] + bia1;
                    const int h = bn >> 7;
                    const int b = m >> 11;
                    const int l = m & (LSEQ - 1);
                    const size_t idx =
                        (((size_t)(b * NH + h) * LSEQ + l) * DH) + (n0 & 127);
                    uint32_t hi, lo;
                    split2(x0, x1, hi, lo);
                    *(uint32_t*)(Ch + idx) = hi;
                    *(uint32_t*)(Cl + idx) = lo;
                }
            }
        }
    } else {
        mainloop_h1(args.vA, args.vB, bm, bn, sbase, acc);
        const float* bias = args.vbias;
        __half* C = args.vC;
#pragma unroll
        for (int mt = 0; mt < 4; mt++) {
#pragma unroll
            for (int nt = 0; nt < 4; nt++) {
                const int m0 = bm + wm * 64 + mt * 16 + (lane >> 2);
                const int n0 = bn + wn * 32 + nt * 8 + (lane & 3) * 2;
                const float bia0 = __ldg(&bias[n0]);
                const float bia1 = __ldg(&bias[n0 + 1]);
#pragma unroll
                for (int half = 0; half < 2; half++) {
                    const int m = m0 + half * 8;
                    const int h = bn >> 7;
                    const int b = m >> 11;
                    const int l = m & (LSEQ - 1);
                    const size_t idx =
                        (((size_t)(b * NH + h) * LSEQ + l) * DH) + (n0 & 127);
                    *(uint32_t*)(C + idx) =
                        pack2h(acc[mt][nt][half * 2] + bia0,
                               acc[mt][nt][half * 2 + 1] + bia1);
                }
            }
        }
    }
}

// ---------------------------------------------------------------------------
// Output projection (round-9 config)
// ---------------------------------------------------------------------------
__global__ __launch_bounds__(256)
void gemm_wo(const __half* __restrict__ A, const __half* __restrict__ B,
             const float* __restrict__ bias, float* __restrict__ C)
{
    extern __shared__ char smb[];
    const uint32_t sbase = smem_u32(smb);
    const int bn = blockIdx.x * 128;
    const int bm = blockIdx.y * 128;
    const int lane = threadIdx.x & 31;
    const int wid = threadIdx.x >> 5;
    const int wm = wid & 1;
    const int wn = wid >> 1;

    float acc[4][4][4];
#pragma unroll
    for (int i = 0; i < 4; i++)
#pragma unroll
        for (int j = 0; j < 4; j++)
#pragma unroll
            for (int c = 0; c < 4; c++) acc[i][j][c] = 0.f;

    mainloop_h1(A, B, bm, bn, sbase, acc);

#pragma unroll
    for (int mt = 0; mt < 4; mt++) {
#pragma unroll
        for (int nt = 0; nt < 4; nt++) {
            const int m0 = bm + wm * 64 + mt * 16 + (lane >> 2);
            const int n0 = bn + wn * 32 + nt * 8 + (lane & 3) * 2;
            const float bia0 = __ldg(&bias[n0]);
            const float bia1 = __ldg(&bias[n0 + 1]);
#pragma unroll
            for (int half = 0; half < 2; half++) {
                const int m = m0 + half * 8;
                *(float2*)(C + (size_t)m * DMODEL + n0) =
                    make_float2(acc[mt][nt][half * 2] + bia0,
                                acc[mt][nt][half * 2 + 1] + bia1);
            }
        }
    }
}

// ---------------------------------------------------------------------------
// Flash attention — round-9 geometry + two subtractive edits:
//  (1) one uniform branch: warps skip k-tiles fully above their diagonal
//  (2) l-sum shfl reduction moved after PV MMA issue (latency hiding;
//      identical summation order -> bit-identical)
// ---------------------------------------------------------------------------
#define NQT (LSEQ / 128)
#define FST_B (3 * 64 * 256)                     // 48 KB
#define FQ_B  (2 * 128 * 256)                    // 64 KB
#define FSMEM_B (FQ_B + 3 * FST_B)               // 208 KB
#define FSCALE 11.31370849898476f

__global__ __launch_bounds__(256, 1)
void flash_mma(const __nv_bfloat16* __restrict__ Qhi,
               const __nv_bfloat16* __restrict__ Qlo,
               const __nv_bfloat16* __restrict__ Khi,
               const __nv_bfloat16* __restrict__ Klo,
               const __half* __restrict__ V,
               __half* __restrict__ O)
{
    extern __shared__ char smb[];
    const uint32_t sbase = smem_u32(smb);
    const uint32_t qlo_s = sbase + 128 * 256;
    const uint32_t stage0 = sbase + FQ_B;

    const int tid = threadIdx.x;
    const int lane = tid & 31;
    const int w = tid >> 5;

    const int bx = blockIdx.x;
    const int qt = (NQT - 1) - (bx >> 5);
    const int hb = bx & 31;
    const int h = hb & 15;
    const int b = hb >> 4;
    const int bh = b * NH + h;
    const int NKT = 2 * (qt + 1);

    const __nv_bfloat16* qh_g = Qhi + (size_t)bh * LSEQ * DH;
    const __nv_bfloat16* ql_g = Qlo + (size_t)bh * LSEQ * DH;
    const __nv_bfloat16* kh_g = Khi + (size_t)bh * LSEQ * DH;
    const __nv_bfloat16* kl_g = Klo + (size_t)bh * LSEQ * DH;
    const __half*        v_g  = V   + (size_t)bh * LSEQ * DH;

    {
#pragma unroll
        for (int j = 0; j < 16; j++) {
            const int c = tid + 256 * j;
            const int t = c >> 11;
            const int u = c & 2047;
            const int r = u >> 4;
            const int q = u & 15;
            const __nv_bfloat16* src = (t ? ql_g : qh_g) +
                (size_t)(qt * 128 + r) * DH + q * 8;
            cp16(sbase + (uint32_t)t * (128 * 256) + sw256(r, q), src);
        }
        CP_COMMIT();
    }

    auto load_stage = [&](int kt, int s) {
        const uint32_t st = stage0 + (uint32_t)s * FST_B;
#pragma unroll
        for (int j = 0; j < 12; j++) {
            const int c = tid + 256 * j;
            const int t = c >> 10;
            const int u = c & 1023;
            const int r = u >> 4;
            const int q = u & 15;
            const char* src =
                (t == 0 ? (const char*)kh_g :
                 t == 1 ? (const char*)kl_g : (const char*)v_g) +
                ((size_t)(kt * 64 + r) * DH + q * 8) * 2;
            cp16(st + (uint32_t)t * 16384 + sw256(r, q), src);
        }
        CP_COMMIT();
    };

    load_stage(0, 0);
    load_stage(1, 1);

    CP_WAIT(2);
    __syncthreads();

    uint32_t qfh[8][4];
#pragma unroll
    for (int ks = 0; ks < 8; ks++) {
        const int row = w * 16 + (lane & 15);
        const int q = ks * 2 + (lane >> 4);
        ldsm_x4(qfh[ks], sbase + sw256(row, q));
    }

    float O_acc[16][4];
#pragma unroll
    for (int nd = 0; nd < 16; nd++)
#pragma unroll
        for (int c = 0; c < 4; c++) O_acc[nd][c] = 0.f;
    float m0 = -3.0e38f, m1 = -3.0e38f, l0 = 0.f, l1 = 0.f;

    const int iq0 = qt * 128 + w * 16 + (lane >> 2);
    const int jcol = (lane & 3) * 2;
    const int rowmax = qt * 128 + w * 16 + 15;

    for (int kt = 0; kt < NKT; kt++) {
        if (kt + 1 < NKT) { CP_WAIT(1); } else { CP_WAIT(0); }
        __syncthreads();
        if (kt + 2 < NKT) load_stage(kt + 2, (kt + 2) % 3);

        const int colbase = kt * 64;
        if (colbase > rowmax) continue;  // fully-masked tile: exact no-op

        const uint32_t st = stage0 + (uint32_t)(kt % 3) * FST_B;
        const uint32_t sKh = st;
        const uint32_t sKl = st + 16384;
        const uint32_t sV  = st + 32768;

        float S[8][4];
#pragma unroll
        for (int nt = 0; nt < 8; nt++)
#pragma unroll
            for (int c = 0; c < 4; c++) S[nt][c] = 0.f;

#pragma unroll
        for (int ks = 0; ks < 8; ks++) {
            uint32_t ql[4];
            {
                const int row = w * 16 + (lane & 15);
                const int q = ks * 2 + (lane >> 4);
                ldsm_x4(ql, qlo_s + sw256(row, q));
            }
            uint32_t kh4[4][4], kl4[4][4];
#pragma unroll
            for (int p = 0; p < 4; p++) {
                const int row = p * 16 + ((lane >> 4) & 1) * 8 + (lane & 7);
                const int q = ks * 2 + ((lane >> 3) & 1);
                ldsm_x4(kh4[p], sKh + sw256(row, q));
                ldsm_x4(kl4[p], sKl + sw256(row, q));
            }
#pragma unroll
            for (int nt = 0; nt < 8; nt++) {
                const uint32_t* kh = &kh4[nt >> 1][(nt & 1) * 2];
                const uint32_t* kl = &kl4[nt >> 1][(nt & 1) * 2];
                mma_bf16(S[nt], qfh[ks], kh);
                mma_bf16(S[nt], qfh[ks], kl);
                mma_bf16(S[nt], ql, kh);
            }
        }

        const bool tilemask = (colbase + 63) > (qt * 128 + w * 16);
#pragma unroll
        for (int nt = 0; nt < 8; nt++) {
#pragma unroll
            for (int c = 0; c < 4; c++) {
                float s = S[nt][c] * FSCALE;
                if (tilemask) {
                    const int i = iq0 + ((c & 2) ? 8 : 0);
                    const int j = colbase + nt * 8 + jcol + (c & 1);
                    if (j > i) s -= 1e7f;
                }
                S[nt][c] = s;
            }
        }

        float tm0 = -3.0e38f, tm1 = -3.0e38f;
#pragma unroll
        for (int nt = 0; nt < 8; nt++) {
            tm0 = fmaxf(tm0, fmaxf(S[nt][0], S[nt][1]));
            tm1 = fmaxf(tm1, fmaxf(S[nt][2], S[nt][3]));
        }
        tm0 = fmaxf(tm0, __shfl_xor_sync(0xffffffffu, tm0, 1));
        tm0 = fmaxf(tm0, __shfl_xor_sync(0xffffffffu, tm0, 2));
        tm1 = fmaxf(tm1, __shfl_xor_sync(0xffffffffu, tm1, 1));
        tm1 = fmaxf(tm1, __shfl_xor_sync(0xffffffffu, tm1, 2));
        const float nm0 = fmaxf(m0, tm0);
        const float nm1 = fmaxf(m1, tm1);

        const unsigned skip =
            __all_sync(0xffffffffu, (nm0 == m0) && (nm1 == m1));
        if (!skip) {
            const float a0 = __expf(m0 - nm0);
            const float a1 = __expf(m1 - nm1);
            l0 *= a0; l1 *= a1;
#pragma unroll
            for (int nd = 0; nd < 16; nd++) {
                O_acc[nd][0] *= a0; O_acc[nd][1] *= a0;
                O_acc[nd][2] *= a1; O_acc[nd][3] *= a1;
            }
            m0 = nm0; m1 = nm1;
        }

        // exp + round (values needed for both PV and l-sum)
#pragma unroll
        for (int nt = 0; nt < 8; nt++) {
            S[nt][0] = __half2float(__float2half_rn(__expf(S[nt][0] - m0)));
            S[nt][1] = __half2float(__float2half_rn(__expf(S[nt][1] - m0)));
            S[nt][2] = __half2float(__float2half_rn(__expf(S[nt][2] - m1)));
            S[nt][3] = __half2float(__float2half_rn(__expf(S[nt][3] - m1)));
        }

        // ---- PV MMAs first (l-reduction hides behind them) ----
#pragma unroll
        for (int ks2 = 0; ks2 < 4; ks2++) {
            const int nt0 = 2 * ks2, nt1 = nt0 + 1;
            uint32_t ph[4];
            ph[0] = pack2h(S[nt0][0], S[nt0][1]);
            ph[1] = pack2h(S[nt0][2], S[nt0][3]);
            ph[2] = pack2h(S[nt1][0], S[nt1][1]);
            ph[3] = pack2h(S[nt1][2], S[nt1][3]);
            const int vrow = ks2 * 16 + (lane & 15);
#pragma unroll
            for (int np = 0; np < 8; np++) {
                uint32_t vv[4];
                const int seg = np * 2 + (lane >> 4);
                ldsm_x4t(vv, sV + sw256(vrow, seg));
                mma_f16(O_acc[2 * np],     ph, vv);
                mma_f16(O_acc[2 * np + 1], ph, vv + 2);
            }
        }

        // ---- l-sum (same summation order as before; issued under MMAs) ----
        float s0 = 0.f, s1 = 0.f;
#pragma unroll
        for (int nt = 0; nt < 8; nt++) {
            s0 += S[nt][0] + S[nt][1];
            s1 += S[nt][2] + S[nt][3];
        }
        s0 += __shfl_xor_sync(0xffffffffu, s0, 1);
        s0 += __shfl_xor_sync(0xffffffffu, s0, 2);
        s1 += __shfl_xor_sync(0xffffffffu, s1, 1);
        s1 += __shfl_xor_sync(0xffffffffu, s1, 2);
        l0 += s0;
        l1 += s1;
    }

    const float inv0 = 1.0f / l0;
    const float inv1 = 1.0f / l1;
    const size_t tok0 = (size_t)b * LSEQ + qt * 128 + w * 16 + (lane >> 2);
    const size_t tok1 = tok0 + 8;
    const int col = h * DH + jcol;
#pragma unroll
    for (int nd = 0; nd < 16; nd++) {
        const int cc = col + nd * 8;
        *(uint32_t*)(O + tok0 * DMODEL + cc) =
            pack2h(O_acc[nd][0] * inv0, O_acc[nd][1] * inv0);
        *(uint32_t*)(O + tok1 * DMODEL + cc) =
            pack2h(O_acc[nd][2] * inv1, O_acc[nd][3] * inv1);
    }
}

// ---------------------------------------------------------------------------
extern "C" void kernel_launch(void* const* d_in, const int* in_sizes, int n_in,
                              void* d_out, int out_size)
{
    (void)in_sizes; (void)n_in; (void)out_size;
    const float* q  = (const float*)d_in[0];
    const float* k  = (const float*)d_in[1];
    const float* v  = (const float*)d_in[2];
    const float* Wq = (const float*)d_in[3];
    const float* bq = (const float*)d_in[4];
    const float* Wk = (const float*)d_in[5];
    const float* bk = (const float*)d_in[6];
    const float* Wv = (const float*)d_in[7];
    const float* bv = (const float*)d_in[8];
    const float* Wo = (const float*)d_in[9];
    const float* bo = (const float*)d_in[10];
    float* out = (float*)d_out;

    __nv_bfloat16 *sq, *sk, *qh2, *kh2, *swq, *swk;
    __half *sv, *sa, *vh2, *swv, *swo;
    cudaGetSymbolAddress((void**)&sq, g_sq);
    cudaGetSymbolAddress((void**)&sk, g_sk);
    cudaGetSymbolAddress((void**)&sv, g_sv);
    cudaGetSymbolAddress((void**)&sa, g_sa);
    cudaGetSymbolAddress((void**)&qh2, g_qh2);
    cudaGetSymbolAddress((void**)&kh2, g_kh2);
    cudaGetSymbolAddress((void**)&vh2, g_vh2);
    cudaGetSymbolAddress((void**)&swq, g_swq);
    cudaGetSymbolAddress((void**)&swk, g_swk);
    cudaGetSymbolAddress((void**)&swv, g_swv);
    cudaGetSymbolAddress((void**)&swo, g_swo);

    cudaFuncSetAttribute(gemm_qkv, cudaFuncAttributeMaxDynamicSharedMemorySize,
                         GS4_B);
    cudaFuncSetAttribute(gemm_wo, cudaFuncAttributeMaxDynamicSharedMemorySize,
                         GSH_B);
    cudaFuncSetAttribute(flash_mma, cudaFuncAttributeMaxDynamicSharedMemorySize,
                         FSMEM_B);

    // ---- prep (round-9 version) ----
    PrepArgs pa;
    pa.src[0] = q;  pa.dst[0] = sq;  pa.n[0] = (int)ACT_ELEMS; pa.type[0] = 0;
    pa.src[1] = k;  pa.dst[1] = sk;  pa.n[1] = (int)ACT_ELEMS; pa.type[1] = 0;
    pa.src[2] = v;  pa.dst[2] = sv;  pa.n[2] = (int)ACT_ELEMS; pa.type[2] = 2;
    pa.src[3] = Wq; pa.dst[3] = swq; pa.n[3] = (int)W_ELEMS;   pa.type[3] = 0;
    pa.src[4] = Wk; pa.dst[4] = swk; pa.n[4] = (int)W_ELEMS;   pa.type[4] = 0;
    pa.src[5] = Wv; pa.dst[5] = swv; pa.n[5] = (int)W_ELEMS;   pa.type[5] = 2;
    pa.src[6] = Wo; pa.dst[6] = swo; pa.n[6] = (int)W_ELEMS;   pa.type[6] = 2;
    for (int i = 0; i < 7; i++) pa.n4[i] = pa.n[i] / 4;
    prep<<<dim3((int)(ACT_ELEMS / 8 / 256), 1, 7), 256>>>(pa);

    // ---- fused Q/K/V projections (round-9 launch) ----
    QKVArgs qa;
    qa.Ah[0] = sq;  qa.Al[0] = sq + ACT_ELEMS;
    qa.Ah[1] = sk;  qa.Al[1] = sk + ACT_ELEMS;
    qa.Bh[0] = swq; qa.Bl[0] = swq + W_ELEMS;
    qa.Bh[1] = swk; qa.Bl[1] = swk + W_ELEMS;
    qa.bias[0] = bq; qa.bias[1] = bk;
    qa.Ch[0] = qh2; qa.Cl[0] = qh2 + ACT_ELEMS;
    qa.Ch[1] = kh2; qa.Cl[1] = kh2 + ACT_ELEMS;
    qa.vA = sv; qa.vB = swv; qa.vbias = bv; qa.vC = vh2;
    gemm_qkv<<<dim3(DMODEL / 128, MTOK / 128, 3), 256, GS4_B>>>(qa);

    // ---- attention ----
    flash_mma<<<NQT * NH * BATCH, 256, FSMEM_B>>>(
        qh2, qh2 + ACT_ELEMS, kh2, kh2 + ACT_ELEMS, vh2, sa);

    // ---- output projection ----
    gemm_wo<<<dim3(DMODEL / 128, MTOK / 128), 256, GSH_B>>>(sa, swo, bo, out);
}

// round 15
// speedup vs baseline: 1.0389x; 1.0043x over previous
#include <cuda_runtime.h>
#include <cuda_bf16.h>
#include <cuda_fp16.h>
#include <cstdint>

#define LSEQ 2048
#define DMODEL 2048
#define NH 16
#define DH 128
#define BATCH 2
#define MTOK (BATCH * LSEQ)                 // 4096
#define ACT_ELEMS ((size_t)MTOK * DMODEL)   // 8388608
#define W_ELEMS ((size_t)DMODEL * DMODEL)   // 4194304

// ---------------- scratch (static device arrays; no allocs) ----------------
__device__ __nv_bfloat16 g_sq[2 * ACT_ELEMS];
__device__ __nv_bfloat16 g_sk[2 * ACT_ELEMS];
__device__ __half        g_sv[ACT_ELEMS];
__device__ __half        g_sa[ACT_ELEMS];
__device__ __nv_bfloat16 g_qh2[2 * ACT_ELEMS];
__device__ __nv_bfloat16 g_kh2[2 * ACT_ELEMS];
__device__ __half        g_vh2[ACT_ELEMS];
__device__ __nv_bfloat16 g_swq[2 * W_ELEMS];
__device__ __nv_bfloat16 g_swk[2 * W_ELEMS];
__device__ __half        g_swv[W_ELEMS];
__device__ __half        g_swo[W_ELEMS];

// ---------------------------- PTX helpers ----------------------------------
__device__ __forceinline__ uint32_t smem_u32(const void* p) {
    uint32_t a;
    asm("{ .reg .u64 t; cvta.to.shared.u64 t, %1; cvt.u32.u64 %0, t; }"
        : "=r"(a) : "l"(p));
    return a;
}

__device__ __forceinline__ void cp16(uint32_t saddr, const void* g) {
    asm volatile("cp.async.cg.shared.global [%0], [%1], 16;"
                 :: "r"(saddr), "l"(g) : "memory");
}
#define CP_COMMIT() asm volatile("cp.async.commit_group;" ::: "memory")
#define CP_WAIT(n)  asm volatile("cp.async.wait_group %0;" :: "n"(n) : "memory")

__device__ __forceinline__ void ldsm_x4(uint32_t* r, uint32_t a) {
    asm volatile("ldmatrix.sync.aligned.m8n8.x4.shared.b16 {%0,%1,%2,%3}, [%4];"
                 : "=r"(r[0]), "=r"(r[1]), "=r"(r[2]), "=r"(r[3]) : "r"(a));
}
__device__ __forceinline__ void ldsm_x4t(uint32_t* r, uint32_t a) {
    asm volatile("ldmatrix.sync.aligned.m8n8.x4.trans.shared.b16 {%0,%1,%2,%3}, [%4];"
                 : "=r"(r[0]), "=r"(r[1]), "=r"(r[2]), "=r"(r[3]) : "r"(a));
}
__device__ __forceinline__ void mma_bf16(float* d, const uint32_t* a,
                                         const uint32_t* b) {
    asm volatile(
        "mma.sync.aligned.m16n8k16.row.col.f32.bf16.bf16.f32 "
        "{%0,%1,%2,%3}, {%4,%5,%6,%7}, {%8,%9}, {%0,%1,%2,%3};"
        : "+f"(d[0]), "+f"(d[1]), "+f"(d[2]), "+f"(d[3])
        : "r"(a[0]), "r"(a[1]), "r"(a[2]), "r"(a[3]), "r"(b[0]), "r"(b[1]));
}
__device__ __forceinline__ void mma_f16(float* d, const uint32_t* a,
                                        const uint32_t* b) {
    asm volatile(
        "mma.sync.aligned.m16n8k16.row.col.f32.f16.f16.f32 "
        "{%0,%1,%2,%3}, {%4,%5,%6,%7}, {%8,%9}, {%0,%1,%2,%3};"
        : "+f"(d[0]), "+f"(d[1]), "+f"(d[2]), "+f"(d[3])
        : "r"(a[0]), "r"(a[1]), "r"(a[2]), "r"(a[3]), "r"(b[0]), "r"(b[1]));
}

__device__ __forceinline__ void split2(float x, float y,
                                       uint32_t& hi, uint32_t& lo) {
    __nv_bfloat16 hx = __float2bfloat16(x);
    __nv_bfloat16 hy = __float2bfloat16(y);
    __nv_bfloat162 h2; h2.x = hx; h2.y = hy;
    hi = *reinterpret_cast<uint32_t*>(&h2);
    __nv_bfloat162 l2;
    l2.x = __float2bfloat16(x - __bfloat162float(hx));
    l2.y = __float2bfloat16(y - __bfloat162float(hy));
    lo = *reinterpret_cast<uint32_t*>(&l2);
}
__device__ __forceinline__ uint32_t pack2h(float x, float y) {
    __half2 h2 = __floats2half2_rn(x, y);
    return *reinterpret_cast<uint32_t*>(&h2);
}

__device__ __forceinline__ uint32_t sw256(int r, int q) {
    return (uint32_t)(r * 256 + ((q ^ (r & 7)) << 4));
}

// ---------------------------------------------------------------------------
// prep: 4 independent load streams per thread (MLP 4); loads issued up-front
// ---------------------------------------------------------------------------
struct PrepArgs {
    const float* src[7];
    void* dst[7];
    int n4[7];
    int n[7];
    int type[7];
};

__device__ __forceinline__ void prep_store(const PrepArgs& a, int z, int i,
                                           const float4& v) {
    const int n = a.n[z];
    if (a.type[z] == 0) {
        uint32_t h0, l0, h1, l1;
        split2(v.x, v.y, h0, l0);
        split2(v.z, v.w, h1, l1);
        uint32_t* hp = (uint32_t*)a.dst[z];
        uint32_t* lp = (uint32_t*)((__nv_bfloat16*)a.dst[z] + n);
        hp[2 * i] = h0; hp[2 * i + 1] = h1;
        lp[2 * i] = l0; lp[2 * i + 1] = l1;
    } else {
        uint32_t* hp = (uint32_t*)a.dst[z];
        hp[2 * i]     = pack2h(v.x, v.y);
        hp[2 * i + 1] = pack2h(v.z, v.w);
    }
}

__global__ __launch_bounds__(256)
void prep(PrepArgs a)
{
    const int z = blockIdx.z;
    const int quarter = a.n4[z] >> 2;
    const int i = blockIdx.x * 256 + threadIdx.x;
    if (i >= quarter) return;
    // issue all 4 loads before any conversion (MLP = 4)
    const float4* s = (const float4*)a.src[z];
    const float4 v0 = s[i];
    const float4 v1 = s[i + quarter];
    const float4 v2 = s[i + 2 * quarter];
    const float4 v3 = s[i + 3 * quarter];
    prep_store(a, z, i,               v0);
    prep_store(a, z, i + quarter,     v1);
    prep_store(a, z, i + 2 * quarter, v2);
    prep_store(a, z, i + 3 * quarter, v3);
}

// ---------------------------------------------------------------------------
// GEMM geometry — round-9 config (128x128 tile, 256 thr, 2 CTA/SM)
// ---------------------------------------------------------------------------
#define TILE_B   8192
#define NSTAGE   3
#define NCHUNK   (DMODEL / 32)
#define STAGE4_B (4 * TILE_B)
#define GS4_B    (NSTAGE * STAGE4_B)   // 96 KB

#define TILEH_B  16384
#define STAGEH_B (2 * TILEH_B)
#define GSH_B    (NSTAGE * STAGEH_B)   // 96 KB
#define NCHUNK64 (DMODEL / 64)

__device__ __forceinline__ void mainloop_bf3(
    const __nv_bfloat16* Ahi, const __nv_bfloat16* Alo,
    const __nv_bfloat16* Bhi, const __nv_bfloat16* Blo,
    int bm, int bn, uint32_t sbase, float acc[4][4][4])
{
    const int tid = threadIdx.x;
    const int lane = tid & 31;
    const int wid = tid >> 5;
    const int wm = wid & 1;
    const int wn = wid >> 1;
    const int r = tid >> 2;
    const int q = tid & 3;

    auto load_stage = [&](int kc, int s) {
        const int k0 = kc * 32;
        const uint32_t st = sbase + (uint32_t)s * STAGE4_B;
        const __nv_bfloat16* srcs[4] = {Ahi, Alo, Bhi, Blo};
        const int row0[4] = {bm, bm, bn, bn};
#pragma unroll
        for (int t = 0; t < 4; t++) {
            const __nv_bfloat16* g0 =
                srcs[t] + (size_t)(row0[t] + r) * DMODEL + k0 + q * 8;
#pragma unroll
            for (int half = 0; half < 2; half++) {
                const int rr = r + half * 64;
                const uint32_t soff = (uint32_t)t * TILE_B + rr * 64 +
                                      ((q ^ ((rr >> 1) & 3)) * 16);
                cp16(st + soff, g0 + (size_t)half * 64 * DMODEL);
            }
        }
    };

    load_stage(0, 0); CP_COMMIT();
    load_stage(1, 1); CP_COMMIT();

    for (int kc = 0; kc < NCHUNK; kc++) {
        const int s = kc % NSTAGE;
        CP_WAIT(1);
        __syncthreads();
        if (kc + 2 < NCHUNK) load_stage(kc + 2, (kc + 2) % NSTAGE);
        CP_COMMIT();

        const uint32_t st = sbase + (uint32_t)s * STAGE4_B;
        const uint32_t sAh = st;
        const uint32_t sAl = st + TILE_B;
        const uint32_t sBh = st + 2 * TILE_B;
        const uint32_t sBl = st + 3 * TILE_B;

#pragma unroll
        for (int ks = 0; ks < 2; ks++) {
            uint32_t ah[4][4], al[4][4], bh4[2][4], bl4[2][4];
#pragma unroll
            for (int mt = 0; mt < 4; mt++) {
                const int row = wm * 64 + mt * 16 + (lane & 15);
                const int kseg = ks * 2 + (lane >> 4);
                const uint32_t off =
                    row * 64 + ((kseg ^ ((row >> 1) & 3)) * 16);
                ldsm_x4(ah[mt], sAh + off);
                ldsm_x4(al[mt], sAl + off);
            }
#pragma unroll
            for (int p = 0; p < 2; p++) {
                const int nrow = wn * 32 + p * 16 + ((lane >> 4) & 1) * 8 +
                                 (lane & 7);
                const int kseg = ks * 2 + ((lane >> 3) & 1);
                const uint32_t off =
                    nrow * 64 + ((kseg ^ ((nrow >> 1) & 3)) * 16);
                ldsm_x4(bh4[p], sBh + off);
                ldsm_x4(bl4[p], sBl + off);
            }
#pragma unroll
            for (int mt = 0; mt < 4; mt++)
#pragma unroll
                for (int nt = 0; nt < 4; nt++) {
                    const uint32_t* bh = &bh4[nt >> 1][(nt & 1) * 2];
                    const uint32_t* bl = &bl4[nt >> 1][(nt & 1) * 2];
                    mma_bf16(acc[mt][nt], ah[mt], bh);
                    mma_bf16(acc[mt][nt], ah[mt], bl);
                    mma_bf16(acc[mt][nt], al[mt], bh);
                }
        }
    }
}

__device__ __forceinline__ void mainloop_h1(
    const __half* A, const __half* B,
    int bm, int bn, uint32_t sbase, float acc[4][4][4])
{
    const int tid = threadIdx.x;
    const int lane = tid & 31;
    const int wid = tid >> 5;
    const int wm = wid & 1;
    const int wn = wid >> 1;

    auto load_stage = [&](int kc, int s) {
        const int k0 = kc * 64;
        const uint32_t st = sbase + (uint32_t)s * STAGEH_B;
#pragma unroll
        for (int j = 0; j < 8; j++) {
            const int c = tid + 256 * j;
            const int t = c >> 10;
            const int u = c & 1023;
            const int r = u >> 3;
            const int q = u & 7;
            const __half* g = (t ? B + (size_t)(bn + r) * DMODEL
                                 : A + (size_t)(bm + r) * DMODEL) + k0 + q * 8;
            cp16(st + (uint32_t)t * TILEH_B + r * 128 +
                 (((q ^ (r & 7)) << 4)), g);
        }
    };

    load_stage(0, 0); CP_COMMIT();
    load_stage(1, 1); CP_COMMIT();

    for (int kc = 0; kc < NCHUNK64; kc++) {
        const int s = kc % NSTAGE;
        CP_WAIT(1);
        __syncthreads();
        if (kc + 2 < NCHUNK64) load_stage(kc + 2, (kc + 2) % NSTAGE);
        CP_COMMIT();

        const uint32_t sA = sbase + (uint32_t)s * STAGEH_B;
        const uint32_t sB = sA + TILEH_B;

#pragma unroll
        for (int ks = 0; ks < 4; ks++) {
            uint32_t ah[4][4], b4[2][4];
#pragma unroll
            for (int mt = 0; mt < 4; mt++) {
                const int row = wm * 64 + mt * 16 + (lane & 15);
                const int kseg = ks * 2 + (lane >> 4);
                ldsm_x4(ah[mt], sA + row * 128 + ((kseg ^ (row & 7)) << 4));
            }
#pragma unroll
            for (int p = 0; p < 2; p++) {
                const int nrow = wn * 32 + p * 16 + ((lane >> 4) & 1) * 8 +
                                 (lane & 7);
                const int kseg = ks * 2 + ((lane >> 3) & 1);
                ldsm_x4(b4[p], sB + nrow * 128 + ((kseg ^ (nrow & 7)) << 4));
            }
#pragma unroll
            for (int mt = 0; mt < 4; mt++)
#pragma unroll
                for (int nt = 0; nt < 4; nt++)
                    mma_f16(acc[mt][nt], ah[mt], &b4[nt >> 1][(nt & 1) * 2]);
        }
    }
}

// ---------------------------------------------------------------------------
// Fused Q/K/V projection GEMM — round-9 launch (grid 16x32x3)
// ---------------------------------------------------------------------------
struct QKVArgs {
    const __nv_bfloat16* Ah[2];
    const __nv_bfloat16* Al[2];
    const __nv_bfloat16* Bh[2];
    const __nv_bfloat16* Bl[2];
    const float* bias[2];
    __nv_bfloat16* Ch[2];
    __nv_bfloat16* Cl[2];
    const __half* vA;
    const __half* vB;
    const float* vbias;
    __half* vC;
};

__global__ __launch_bounds__(256)
void gemm_qkv(QKVArgs args)
{
    extern __shared__ char smb[];
    const uint32_t sbase = smem_u32(smb);
    const int sel = blockIdx.z;
    const int bn = blockIdx.x * 128;
    const int bm = blockIdx.y * 128;
    const int lane = threadIdx.x & 31;
    const int wid = threadIdx.x >> 5;
    const int wm = wid & 1;
    const int wn = wid >> 1;

    float acc[4][4][4];
#pragma unroll
    for (int i = 0; i < 4; i++)
#pragma unroll
        for (int j = 0; j < 4; j++)
#pragma unroll
            for (int c = 0; c < 4; c++) acc[i][j][c] = 0.f;

    if (sel < 2) {
        mainloop_bf3(args.Ah[sel], args.Al[sel], args.Bh[sel], args.Bl[sel],
                     bm, bn, sbase, acc);
        const float* bias = args.bias[sel];
        __nv_bfloat16* Ch = args.Ch[sel];
        __nv_bfloat16* Cl = args.Cl[sel];
#pragma unroll
        for (int mt = 0; mt < 4; mt++) {
#pragma unroll
            for (int nt = 0; nt < 4; nt++) {
                const int m0 = bm + wm * 64 + mt * 16 + (lane >> 2);
                const int n0 = bn + wn * 32 + nt * 8 + (lane & 3) * 2;
                const float bia0 = __ldg(&bias[n0]);
                const float bia1 = __ldg(&bias[n0 + 1]);
#pragma unroll
                for (int half = 0; half < 2; half++) {
                    const int m = m0 + half * 8;
                    const float x0 = acc[mt][nt][half * 2] + bia0;
                    const float x1 = acc[mt][nt][half * 2 + 1] + bia1;
                    const int h = bn >> 7;
                    const int b = m >> 11;
                    const int l = m & (LSEQ - 1);
                    const size_t idx =
                        (((size_t)(b * NH + h) * LSEQ + l) * DH) + (n0 & 127);
                    uint32_t hi, lo;
                    split2(x0, x1, hi, lo);
                    *(uint32_t*)(Ch + idx) = hi;
                    *(uint32_t*)(Cl + idx) = lo;
                }
            }
        }
    } else {
        mainloop_h1(args.vA, args.vB, bm, bn, sbase, acc);
        const float* bias = args.vbias;
        __half* C = args.vC;
#pragma unroll
        for (int mt = 0; mt < 4; mt++) {
#pragma unroll
            for (int nt = 0; nt < 4; nt++) {
                const int m0 = bm + wm * 64 + mt * 16 + (lane >> 2);
                const int n0 = bn + wn * 32 + nt * 8 + (lane & 3) * 2;
                const float bia0 = __ldg(&bias[n0]);
                const float bia1 = __ldg(&bias[n0 + 1]);
#pragma unroll
                for (int half = 0; half < 2; half++) {
                    const int m = m0 + half * 8;
                    const int h = bn >> 7;
                    const int b = m >> 11;
                    const int l = m & (LSEQ - 1);
                    const size_t idx =
                        (((size_t)(b * NH + h) * LSEQ + l) * DH) + (n0 & 127);
                    *(uint32_t*)(C + idx) =
                        pack2h(acc[mt][nt][half * 2] + bia0,
                               acc[mt][nt][half * 2 + 1] + bia1);
                }
            }
        }
    }
}

// ---------------------------------------------------------------------------
// Output projection (round-9 config)
// ---------------------------------------------------------------------------
__global__ __launch_bounds__(256)
void gemm_wo(const __half* __restrict__ A, const __half* __restrict__ B,
             const float* __restrict__ bias, float* __restrict__ C)
{
    extern __shared__ char smb[];
    const uint32_t sbase = smem_u32(smb);
    const int bn = blockIdx.x * 128;
    const int bm = blockIdx.y * 128;
    const int lane = threadIdx.x & 31;
    const int wid = threadIdx.x >> 5;
    const int wm = wid & 1;
    const int wn = wid >> 1;

    float acc[4][4][4];
#pragma unroll
    for (int i = 0; i < 4; i++)
#pragma unroll
        for (int j = 0; j < 4; j++)
#pragma unroll
            for (int c = 0; c < 4; c++) acc[i][j][c] = 0.f;

    mainloop_h1(A, B, bm, bn, sbase, acc);

#pragma unroll
    for (int mt = 0; mt < 4; mt++) {
#pragma unroll
        for (int nt = 0; nt < 4; nt++) {
            const int m0 = bm + wm * 64 + mt * 16 + (lane >> 2);
            const int n0 = bn + wn * 32 + nt * 8 + (lane & 3) * 2;
            const float bia0 = __ldg(&bias[n0]);
            const float bia1 = __ldg(&bias[n0 + 1]);
#pragma unroll
            for (int half = 0; half < 2; half++) {
                const int m = m0 + half * 8;
                *(float2*)(C + (size_t)m * DMODEL + n0) =
                    make_float2(acc[mt][nt][half * 2] + bia0,
                                acc[mt][nt][half * 2 + 1] + bia1);
            }
        }
    }
}

// ---------------------------------------------------------------------------
// Flash attention — round-14 version (tile-level causal skip, deferred l-sum)
// ---------------------------------------------------------------------------
#define NQT (LSEQ / 128)
#define FST_B (3 * 64 * 256)                     // 48 KB
#define FQ_B  (2 * 128 * 256)                    // 64 KB
#define FSMEM_B (FQ_B + 3 * FST_B)               // 208 KB
#define FSCALE 11.31370849898476f

__global__ __launch_bounds__(256, 1)
void flash_mma(const __nv_bfloat16* __restrict__ Qhi,
               const __nv_bfloat16* __restrict__ Qlo,
               const __nv_bfloat16* __restrict__ Khi,
               const __nv_bfloat16* __restrict__ Klo,
               const __half* __restrict__ V,
               __half* __restrict__ O)
{
    extern __shared__ char smb[];
    const uint32_t sbase = smem_u32(smb);
    const uint32_t qlo_s = sbase + 128 * 256;
    const uint32_t stage0 = sbase + FQ_B;

    const int tid = threadIdx.x;
    const int lane = tid & 31;
    const int w = tid >> 5;

    const int bx = blockIdx.x;
    const int qt = (NQT - 1) - (bx >> 5);
    const int hb = bx & 31;
    const int h = hb & 15;
    const int b = hb >> 4;
    const int bh = b * NH + h;
    const int NKT = 2 * (qt + 1);

    const __nv_bfloat16* qh_g = Qhi + (size_t)bh * LSEQ * DH;
    const __nv_bfloat16* ql_g = Qlo + (size_t)bh * LSEQ * DH;
    const __nv_bfloat16* kh_g = Khi + (size_t)bh * LSEQ * DH;
    const __nv_bfloat16* kl_g = Klo + (size_t)bh * LSEQ * DH;
    const __half*        v_g  = V   + (size_t)bh * LSEQ * DH;

    {
#pragma unroll
        for (int j = 0; j < 16; j++) {
            const int c = tid + 256 * j;
            const int t = c >> 11;
            const int u = c & 2047;
            const int r = u >> 4;
            const int q = u & 15;
            const __nv_bfloat16* src = (t ? ql_g : qh_g) +
                (size_t)(qt * 128 + r) * DH + q * 8;
            cp16(sbase + (uint32_t)t * (128 * 256) + sw256(r, q), src);
        }
        CP_COMMIT();
    }

    auto load_stage = [&](int kt, int s) {
        const uint32_t st = stage0 + (uint32_t)s * FST_B;
#pragma unroll
        for (int j = 0; j < 12; j++) {
            const int c = tid + 256 * j;
            const int t = c >> 10;
            const int u = c & 1023;
            const int r = u >> 4;
            const int q = u & 15;
            const char* src =
                (t == 0 ? (const char*)kh_g :
                 t == 1 ? (const char*)kl_g : (const char*)v_g) +
                ((size_t)(kt * 64 + r) * DH + q * 8) * 2;
            cp16(st + (uint32_t)t * 16384 + sw256(r, q), src);
        }
        CP_COMMIT();
    };

    load_stage(0, 0);
    load_stage(1, 1);

    CP_WAIT(2);
    __syncthreads();

    uint32_t qfh[8][4];
#pragma unroll
    for (int ks = 0; ks < 8; ks++) {
        const int row = w * 16 + (lane & 15);
        const int q = ks * 2 + (lane >> 4);
        ldsm_x4(qfh[ks], sbase + sw256(row, q));
    }

    float O_acc[16][4];
#pragma unroll
    for (int nd = 0; nd < 16; nd++)
#pragma unroll
        for (int c = 0; c < 4; c++) O_acc[nd][c] = 0.f;
    float m0 = -3.0e38f, m1 = -3.0e38f, l0 = 0.f, l1 = 0.f;

    const int iq0 = qt * 128 + w * 16 + (lane >> 2);
    const int jcol = (lane & 3) * 2;
    const int rowmax = qt * 128 + w * 16 + 15;

    for (int kt = 0; kt < NKT; kt++) {
        if (kt + 1 < NKT) { CP_WAIT(1); } else { CP_WAIT(0); }
        __syncthreads();
        if (kt + 2 < NKT) load_stage(kt + 2, (kt + 2) % 3);

        const int colbase = kt * 64;
        if (colbase > rowmax) continue;  // fully-masked tile: exact no-op

        const uint32_t st = stage0 + (uint32_t)(kt % 3) * FST_B;
        const uint32_t sKh = st;
        const uint32_t sKl = st + 16384;
        const uint32_t sV  = st + 32768;

        float S[8][4];
#pragma unroll
        for (int nt = 0; nt < 8; nt++)
#pragma unroll
            for (int c = 0; c < 4; c++) S[nt][c] = 0.f;

#pragma unroll
        for (int ks = 0; ks < 8; ks++) {
            uint32_t ql[4];
            {
                const int row = w * 16 + (lane & 15);
                const int q = ks * 2 + (lane >> 4);
                ldsm_x4(ql, qlo_s + sw256(row, q));
            }
            uint32_t kh4[4][4], kl4[4][4];
#pragma unroll
            for (int p = 0; p < 4; p++) {
                const int row = p * 16 + ((lane >> 4) & 1) * 8 + (lane & 7);
                const int q = ks * 2 + ((lane >> 3) & 1);
                ldsm_x4(kh4[p], sKh + sw256(row, q));
                ldsm_x4(kl4[p], sKl + sw256(row, q));
            }
#pragma unroll
            for (int nt = 0; nt < 8; nt++) {
                const uint32_t* kh = &kh4[nt >> 1][(nt & 1) * 2];
                const uint32_t* kl = &kl4[nt >> 1][(nt & 1) * 2];
                mma_bf16(S[nt], qfh[ks], kh);
                mma_bf16(S[nt], qfh[ks], kl);
                mma_bf16(S[nt], ql, kh);
            }
        }

        const bool tilemask = (colbase + 63) > (qt * 128 + w * 16);
#pragma unroll
        for (int nt = 0; nt < 8; nt++) {
#pragma unroll
            for (int c = 0; c < 4; c++) {
                float s = S[nt][c] * FSCALE;
                if (tilemask) {
                    const int i = iq0 + ((c & 2) ? 8 : 0);
                    const int j = colbase + nt * 8 + jcol + (c & 1);
                    if (j > i) s -= 1e7f;
                }
                S[nt][c] = s;
            }
        }

        float tm0 = -3.0e38f, tm1 = -3.0e38f;
#pragma unroll
        for (int nt = 0; nt < 8; nt++) {
            tm0 = fmaxf(tm0, fmaxf(S[nt][0], S[nt][1]));
            tm1 = fmaxf(tm1, fmaxf(S[nt][2], S[nt][3]));
        }
        tm0 = fmaxf(tm0, __shfl_xor_sync(0xffffffffu, tm0, 1));
        tm0 = fmaxf(tm0, __shfl_xor_sync(0xffffffffu, tm0, 2));
        tm1 = fmaxf(tm1, __shfl_xor_sync(0xffffffffu, tm1, 1));
        tm1 = fmaxf(tm1, __shfl_xor_sync(0xffffffffu, tm1, 2));
        const float nm0 = fmaxf(m0, tm0);
        const float nm1 = fmaxf(m1, tm1);

        const unsigned skip =
            __all_sync(0xffffffffu, (nm0 == m0) && (nm1 == m1));
        if (!skip) {
            const float a0 = __expf(m0 - nm0);
            const float a1 = __expf(m1 - nm1);
            l0 *= a0; l1 *= a1;
#pragma unroll
            for (int nd = 0; nd < 16; nd++) {
                O_acc[nd][0] *= a0; O_acc[nd][1] *= a0;
                O_acc[nd][2] *= a1; O_acc[nd][3] *= a1;
            }
            m0 = nm0; m1 = nm1;
        }

#pragma unroll
        for (int nt = 0; nt < 8; nt++) {
            S[nt][0] = __half2float(__float2half_rn(__expf(S[nt][0] - m0)));
            S[nt][1] = __half2float(__float2half_rn(__expf(S[nt][1] - m0)));
            S[nt][2] = __half2float(__float2half_rn(__expf(S[nt][2] - m1)));
            S[nt][3] = __half2float(__float2half_rn(__expf(S[nt][3] - m1)));
        }

        // PV MMAs first (l-reduction hides behind them)
#pragma unroll
        for (int ks2 = 0; ks2 < 4; ks2++) {
            const int nt0 = 2 * ks2, nt1 = nt0 + 1;
            uint32_t ph[4];
            ph[0] = pack2h(S[nt0][0], S[nt0][1]);
            ph[1] = pack2h(S[nt0][2], S[nt0][3]);
            ph[2] = pack2h(S[nt1][0], S[nt1][1]);
            ph[3] = pack2h(S[nt1][2], S[nt1][3]);
            const int vrow = ks2 * 16 + (lane & 15);
#pragma unroll
            for (int np = 0; np < 8; np++) {
                uint32_t vv[4];
                const int seg = np * 2 + (lane >> 4);
                ldsm_x4t(vv, sV + sw256(vrow, seg));
                mma_f16(O_acc[2 * np],     ph, vv);
                mma_f16(O_acc[2 * np + 1], ph, vv + 2);
            }
        }

        float s0 = 0.f, s1 = 0.f;
#pragma unroll
        for (int nt = 0; nt < 8; nt++) {
            s0 += S[nt][0] + S[nt][1];
            s1 += S[nt][2] + S[nt][3];
        }
        s0 += __shfl_xor_sync(0xffffffffu, s0, 1);
        s0 += __shfl_xor_sync(0xffffffffu, s0, 2);
        s1 += __shfl_xor_sync(0xffffffffu, s1, 1);
        s1 += __shfl_xor_sync(0xffffffffu, s1, 2);
        l0 += s0;
        l1 += s1;
    }

    const float inv0 = 1.0f / l0;
    const float inv1 = 1.0f / l1;
    const size_t tok0 = (size_t)b * LSEQ + qt * 128 + w * 16 + (lane >> 2);
    const size_t tok1 = tok0 + 8;
    const int col = h * DH + jcol;
#pragma unroll
    for (int nd = 0; nd < 16; nd++) {
        const int cc = col + nd * 8;
        *(uint32_t*)(O + tok0 * DMODEL + cc) =
            pack2h(O_acc[nd][0] * inv0, O_acc[nd][1] * inv0);
        *(uint32_t*)(O + tok1 * DMODEL + cc) =
            pack2h(O_acc[nd][2] * inv1, O_acc[nd][3] * inv1);
    }
}

// ---------------------------------------------------------------------------
extern "C" void kernel_launch(void* const* d_in, const int* in_sizes, int n_in,
                              void* d_out, int out_size)
{
    (void)in_sizes; (void)n_in; (void)out_size;
    const float* q  = (const float*)d_in[0];
    const float* k  = (const float*)d_in[1];
    const float* v  = (const float*)d_in[2];
    const float* Wq = (const float*)d_in[3];
    const float* bq = (const float*)d_in[4];
    const float* Wk = (const float*)d_in[5];
    const float* bk = (const float*)d_in[6];
    const float* Wv = (const float*)d_in[7];
    const float* bv = (const float*)d_in[8];
    const float* Wo = (const float*)d_in[9];
    const float* bo = (const float*)d_in[10];
    float* out = (float*)d_out;

    __nv_bfloat16 *sq, *sk, *qh2, *kh2, *swq, *swk;
    __half *sv, *sa, *vh2, *swv, *swo;
    cudaGetSymbolAddress((void**)&sq, g_sq);
    cudaGetSymbolAddress((void**)&sk, g_sk);
    cudaGetSymbolAddress((void**)&sv, g_sv);
    cudaGetSymbolAddress((void**)&sa, g_sa);
    cudaGetSymbolAddress((void**)&qh2, g_qh2);
    cudaGetSymbolAddress((void**)&kh2, g_kh2);
    cudaGetSymbolAddress((void**)&vh2, g_vh2);
    cudaGetSymbolAddress((void**)&swq, g_swq);
    cudaGetSymbolAddress((void**)&swk, g_swk);
    cudaGetSymbolAddress((void**)&swv, g_swv);
    cudaGetSymbolAddress((void**)&swo, g_swo);

    cudaFuncSetAttribute(gemm_qkv, cudaFuncAttributeMaxDynamicSharedMemorySize,
                         GS4_B);
    cudaFuncSetAttribute(gemm_wo, cudaFuncAttributeMaxDynamicSharedMemorySize,
                         GSH_B);
    cudaFuncSetAttribute(flash_mma, cudaFuncAttributeMaxDynamicSharedMemorySize,
                         FSMEM_B);

    // ---- prep (MLP 4) ----
    PrepArgs pa;
    pa.src[0] = q;  pa.dst[0] = sq;  pa.n[0] = (int)ACT_ELEMS; pa.type[0] = 0;
    pa.src[1] = k;  pa.dst[1] = sk;  pa.n[1] = (int)ACT_ELEMS; pa.type[1] = 0;
    pa.src[2] = v;  pa.dst[2] = sv;  pa.n[2] = (int)ACT_ELEMS; pa.type[2] = 2;
    pa.src[3] = Wq; pa.dst[3] = swq; pa.n[3] = (int)W_ELEMS;   pa.type[3] = 0;
    pa.src[4] = Wk; pa.dst[4] = swk; pa.n[4] = (int)W_ELEMS;   pa.type[4] = 0;
    pa.src[5] = Wv; pa.dst[5] = swv; pa.n[5] = (int)W_ELEMS;   pa.type[5] = 2;
    pa.src[6] = Wo; pa.dst[6] = swo; pa.n[6] = (int)W_ELEMS;   pa.type[6] = 2;
    for (int i = 0; i < 7; i++) pa.n4[i] = pa.n[i] / 4;
    prep<<<dim3((int)(ACT_ELEMS / 16 / 256), 1, 7), 256>>>(pa);

    // ---- fused Q/K/V projections (round-9 launch) ----
    QKVArgs qa;
    qa.Ah[0] = sq;  qa.Al[0] = sq + ACT_ELEMS;
    qa.Ah[1] = sk;  qa.Al[1] = sk + ACT_ELEMS;
    qa.Bh[0] = swq; qa.Bl[0] = swq + W_ELEMS;
    qa.Bh[1] = swk; qa.Bl[1] = swk + W_ELEMS;
    qa.bias[0] = bq; qa.bias[1] = bk;
    qa.Ch[0] = qh2; qa.Cl[0] = qh2 + ACT_ELEMS;
    qa.Ch[1] = kh2; qa.Cl[1] = kh2 + ACT_ELEMS;
    qa.vA = sv; qa.vB = swv; qa.vbias = bv; qa.vC = vh2;
    gemm_qkv<<<dim3(DMODEL / 128, MTOK / 128, 3), 256, GS4_B>>>(qa);

    // ---- attention ----
    flash_mma<<<NQT * NH * BATCH, 256, FSMEM_B>>>(
        qh2, qh2 + ACT_ELEMS, kh2, kh2 + ACT_ELEMS, vh2, sa);

    // ---- output projection ----
    gemm_wo<<<dim3(DMODEL / 128, MTOK / 128), 256, GSH_B>>>(sa, swo, bo, out);
}

// round 16
// speedup vs baseline: 1.1453x; 1.1024x over previous
#include <cuda_runtime.h>
#include <cuda_bf16.h>
#include <cuda_fp16.h>
#include <cstdint>

#define LSEQ 2048
#define DMODEL 2048
#define NH 16
#define DH 128
#define BATCH 2
#define MTOK (BATCH * LSEQ)                 // 4096
#define ACT_ELEMS ((size_t)MTOK * DMODEL)   // 8388608
#define W_ELEMS ((size_t)DMODEL * DMODEL)   // 4194304

// ---------------- scratch (static device arrays; no allocs) ----------------
__device__ __nv_bfloat16 g_sq[2 * ACT_ELEMS];
__device__ __nv_bfloat16 g_sk[2 * ACT_ELEMS];
__device__ __half        g_sv[ACT_ELEMS];
__device__ __half        g_sa[ACT_ELEMS];
__device__ __nv_bfloat16 g_qh2[2 * ACT_ELEMS];
__device__ __nv_bfloat16 g_kh2[2 * ACT_ELEMS];
__device__ __half        g_vh2[ACT_ELEMS];
__device__ __nv_bfloat16 g_swq[2 * W_ELEMS];
__device__ __nv_bfloat16 g_swk[2 * W_ELEMS];
__device__ __half        g_swv[W_ELEMS];
__device__ __half        g_swo[W_ELEMS];

// ---------------------------- PTX helpers ----------------------------------
__device__ __forceinline__ uint32_t smem_u32(const void* p) {
    uint32_t a;
    asm("{ .reg .u64 t; cvta.to.shared.u64 t, %1; cvt.u32.u64 %0, t; }"
        : "=r"(a) : "l"(p));
    return a;
}

__device__ __forceinline__ void cp16(uint32_t saddr, const void* g) {
    asm volatile("cp.async.cg.shared.global [%0], [%1], 16;"
                 :: "r"(saddr), "l"(g) : "memory");
}
#define CP_COMMIT() asm volatile("cp.async.commit_group;" ::: "memory")
#define CP_WAIT(n)  asm volatile("cp.async.wait_group %0;" :: "n"(n) : "memory")

__device__ __forceinline__ void ldsm_x4(uint32_t* r, uint32_t a) {
    asm volatile("ldmatrix.sync.aligned.m8n8.x4.shared.b16 {%0,%1,%2,%3}, [%4];"
                 : "=r"(r[0]), "=r"(r[1]), "=r"(r[2]), "=r"(r[3]) : "r"(a));
}
__device__ __forceinline__ void ldsm_x4t(uint32_t* r, uint32_t a) {
    asm volatile("ldmatrix.sync.aligned.m8n8.x4.trans.shared.b16 {%0,%1,%2,%3}, [%4];"
                 : "=r"(r[0]), "=r"(r[1]), "=r"(r[2]), "=r"(r[3]) : "r"(a));
}
__device__ __forceinline__ void mma_bf16(float* d, const uint32_t* a,
                                         const uint32_t* b) {
    asm volatile(
        "mma.sync.aligned.m16n8k16.row.col.f32.bf16.bf16.f32 "
        "{%0,%1,%2,%3}, {%4,%5,%6,%7}, {%8,%9}, {%0,%1,%2,%3};"
        : "+f"(d[0]), "+f"(d[1]), "+f"(d[2]), "+f"(d[3])
        : "r"(a[0]), "r"(a[1]), "r"(a[2]), "r"(a[3]), "r"(b[0]), "r"(b[1]));
}
__device__ __forceinline__ void mma_f16(float* d, const uint32_t* a,
                                        const uint32_t* b) {
    asm volatile(
        "mma.sync.aligned.m16n8k16.row.col.f32.f16.f16.f32 "
        "{%0,%1,%2,%3}, {%4,%5,%6,%7}, {%8,%9}, {%0,%1,%2,%3};"
        : "+f"(d[0]), "+f"(d[1]), "+f"(d[2]), "+f"(d[3])
        : "r"(a[0]), "r"(a[1]), "r"(a[2]), "r"(a[3]), "r"(b[0]), "r"(b[1]));
}

__device__ __forceinline__ void split2(float x, float y,
                                       uint32_t& hi, uint32_t& lo) {
    __nv_bfloat16 hx = __float2bfloat16(x);
    __nv_bfloat16 hy = __float2bfloat16(y);
    __nv_bfloat162 h2; h2.x = hx; h2.y = hy;
    hi = *reinterpret_cast<uint32_t*>(&h2);
    __nv_bfloat162 l2;
    l2.x = __float2bfloat16(x - __bfloat162float(hx));
    l2.y = __float2bfloat16(y - __bfloat162float(hy));
    lo = *reinterpret_cast<uint32_t*>(&l2);
}
__device__ __forceinline__ uint32_t pack2h(float x, float y) {
    __half2 h2 = __floats2half2_rn(x, y);
    return *reinterpret_cast<uint32_t*>(&h2);
}

__device__ __forceinline__ uint32_t sw256(int r, int q) {
    return (uint32_t)(r * 256 + ((q ^ (r & 7)) << 4));
}

// ---------------------------------------------------------------------------
// prep: 4 independent load streams per thread (MLP 4)
// ---------------------------------------------------------------------------
struct PrepArgs {
    const float* src[7];
    void* dst[7];
    int n4[7];
    int n[7];
    int type[7];
};

__device__ __forceinline__ void prep_store(const PrepArgs& a, int z, int i,
                                           const float4& v) {
    const int n = a.n[z];
    if (a.type[z] == 0) {
        uint32_t h0, l0, h1, l1;
        split2(v.x, v.y, h0, l0);
        split2(v.z, v.w, h1, l1);
        uint32_t* hp = (uint32_t*)a.dst[z];
        uint32_t* lp = (uint32_t*)((__nv_bfloat16*)a.dst[z] + n);
        hp[2 * i] = h0; hp[2 * i + 1] = h1;
        lp[2 * i] = l0; lp[2 * i + 1] = l1;
    } else {
        uint32_t* hp = (uint32_t*)a.dst[z];
        hp[2 * i]     = pack2h(v.x, v.y);
        hp[2 * i + 1] = pack2h(v.z, v.w);
    }
}

__global__ __launch_bounds__(256)
void prep(PrepArgs a)
{
    const int z = blockIdx.z;
    const int quarter = a.n4[z] >> 2;
    const int i = blockIdx.x * 256 + threadIdx.x;
    if (i >= quarter) return;
    const float4* s = (const float4*)a.src[z];
    const float4 v0 = s[i];
    const float4 v1 = s[i + quarter];
    const float4 v2 = s[i + 2 * quarter];
    const float4 v3 = s[i + 3 * quarter];
    prep_store(a, z, i,               v0);
    prep_store(a, z, i + quarter,     v1);
    prep_store(a, z, i + 2 * quarter, v2);
    prep_store(a, z, i + 3 * quarter, v3);
}

// ---------------------------------------------------------------------------
// GEMM geometry — round-9 config (128x128 tile, 256 thr, 2 CTA/SM)
// ---------------------------------------------------------------------------
#define TILE_B   8192
#define NSTAGE   3
#define NCHUNK   (DMODEL / 32)
#define STAGE4_B (4 * TILE_B)
#define GS4_B    (NSTAGE * STAGE4_B)   // 96 KB

#define TILEH_B  16384
#define STAGEH_B (2 * TILEH_B)
#define GSH_B    (NSTAGE * STAGEH_B)   // 96 KB
#define NCHUNK64 (DMODEL / 64)

__device__ __forceinline__ void mainloop_bf3(
    const __nv_bfloat16* Ahi, const __nv_bfloat16* Alo,
    const __nv_bfloat16* Bhi, const __nv_bfloat16* Blo,
    int bm, int bn, uint32_t sbase, float acc[4][4][4])
{
    const int tid = threadIdx.x;
    const int lane = tid & 31;
    const int wid = tid >> 5;
    const int wm = wid & 1;
    const int wn = wid >> 1;
    const int r = tid >> 2;
    const int q = tid & 3;

    auto load_stage = [&](int kc, int s) {
        const int k0 = kc * 32;
        const uint32_t st = sbase + (uint32_t)s * STAGE4_B;
        const __nv_bfloat16* srcs[4] = {Ahi, Alo, Bhi, Blo};
        const int row0[4] = {bm, bm, bn, bn};
#pragma unroll
        for (int t = 0; t < 4; t++) {
            const __nv_bfloat16* g0 =
                srcs[t] + (size_t)(row0[t] + r) * DMODEL + k0 + q * 8;
#pragma unroll
            for (int half = 0; half < 2; half++) {
                const int rr = r + half * 64;
                const uint32_t soff = (uint32_t)t * TILE_B + rr * 64 +
                                      ((q ^ ((rr >> 1) & 3)) * 16);
                cp16(st + soff, g0 + (size_t)half * 64 * DMODEL);
            }
        }
    };

    load_stage(0, 0); CP_COMMIT();
    load_stage(1, 1); CP_COMMIT();

    for (int kc = 0; kc < NCHUNK; kc++) {
        const int s = kc % NSTAGE;
        CP_WAIT(1);
        __syncthreads();
        if (kc + 2 < NCHUNK) load_stage(kc + 2, (kc + 2) % NSTAGE);
        CP_COMMIT();

        const uint32_t st = sbase + (uint32_t)s * STAGE4_B;
        const uint32_t sAh = st;
        const uint32_t sAl = st + TILE_B;
        const uint32_t sBh = st + 2 * TILE_B;
        const uint32_t sBl = st + 3 * TILE_B;

#pragma unroll
        for (int ks = 0; ks < 2; ks++) {
            uint32_t ah[4][4], al[4][4], bh4[2][4], bl4[2][4];
#pragma unroll
            for (int mt = 0; mt < 4; mt++) {
                const int row = wm * 64 + mt * 16 + (lane & 15);
                const int kseg = ks * 2 + (lane >> 4);
                const uint32_t off =
                    row * 64 + ((kseg ^ ((row >> 1) & 3)) * 16);
                ldsm_x4(ah[mt], sAh + off);
                ldsm_x4(al[mt], sAl + off);
            }
#pragma unroll
            for (int p = 0; p < 2; p++) {
                const int nrow = wn * 32 + p * 16 + ((lane >> 4) & 1) * 8 +
                                 (lane & 7);
                const int kseg = ks * 2 + ((lane >> 3) & 1);
                const uint32_t off =
                    nrow * 64 + ((kseg ^ ((nrow >> 1) & 3)) * 16);
                ldsm_x4(bh4[p], sBh + off);
                ldsm_x4(bl4[p], sBl + off);
            }
#pragma unroll
            for (int mt = 0; mt < 4; mt++)
#pragma unroll
                for (int nt = 0; nt < 4; nt++) {
                    const uint32_t* bh = &bh4[nt >> 1][(nt & 1) * 2];
                    const uint32_t* bl = &bl4[nt >> 1][(nt & 1) * 2];
                    mma_bf16(acc[mt][nt], ah[mt], bh);
                    mma_bf16(acc[mt][nt], ah[mt], bl);
                    mma_bf16(acc[mt][nt], al[mt], bh);
                }
        }
    }
}

__device__ __forceinline__ void mainloop_h1(
    const __half* A, const __half* B,
    int bm, int bn, uint32_t sbase, float acc[4][4][4])
{
    const int tid = threadIdx.x;
    const int lane = tid & 31;
    const int wid = tid >> 5;
    const int wm = wid & 1;
    const int wn = wid >> 1;

    auto load_stage = [&](int kc, int s) {
        const int k0 = kc * 64;
        const uint32_t st = sbase + (uint32_t)s * STAGEH_B;
#pragma unroll
        for (int j = 0; j < 8; j++) {
            const int c = tid + 256 * j;
            const int t = c >> 10;
            const int u = c & 1023;
            const int r = u >> 3;
            const int q = u & 7;
            const __half* g = (t ? B + (size_t)(bn + r) * DMODEL
                                 : A + (size_t)(bm + r) * DMODEL) + k0 + q * 8;
            cp16(st + (uint32_t)t * TILEH_B + r * 128 +
                 (((q ^ (r & 7)) << 4)), g);
        }
    };

    load_stage(0, 0); CP_COMMIT();
    load_stage(1, 1); CP_COMMIT();

    for (int kc = 0; kc < NCHUNK64; kc++) {
        const int s = kc % NSTAGE;
        CP_WAIT(1);
        __syncthreads();
        if (kc + 2 < NCHUNK64) load_stage(kc + 2, (kc + 2) % NSTAGE);
        CP_COMMIT();

        const uint32_t sA = sbase + (uint32_t)s * STAGEH_B;
        const uint32_t sB = sA + TILEH_B;

#pragma unroll
        for (int ks = 0; ks < 4; ks++) {
            uint32_t ah[4][4], b4[2][4];
#pragma unroll
            for (int mt = 0; mt < 4; mt++) {
                const int row = wm * 64 + mt * 16 + (lane & 15);
                const int kseg = ks * 2 + (lane >> 4);
                ldsm_x4(ah[mt], sA + row * 128 + ((kseg ^ (row & 7)) << 4));
            }
#pragma unroll
            for (int p = 0; p < 2; p++) {
                const int nrow = wn * 32 + p * 16 + ((lane >> 4) & 1) * 8 +
                                 (lane & 7);
                const int kseg = ks * 2 + ((lane >> 3) & 1);
                ldsm_x4(b4[p], sB + nrow * 128 + ((kseg ^ (nrow & 7)) << 4));
            }
#pragma unroll
            for (int mt = 0; mt < 4; mt++)
#pragma unroll
                for (int nt = 0; nt < 4; nt++)
                    mma_f16(acc[mt][nt], ah[mt], &b4[nt >> 1][(nt & 1) * 2]);
        }
    }
}

// ---------------------------------------------------------------------------
// Fused Q/K/V projection GEMM — round-9 launch; bias hoisted above mt loop
// ---------------------------------------------------------------------------
struct QKVArgs {
    const __nv_bfloat16* Ah[2];
    const __nv_bfloat16* Al[2];
    const __nv_bfloat16* Bh[2];
    const __nv_bfloat16* Bl[2];
    const float* bias[2];
    __nv_bfloat16* Ch[2];
    __nv_bfloat16* Cl[2];
    const __half* vA;
    const __half* vB;
    const float* vbias;
    __half* vC;
};

__global__ __launch_bounds__(256)
void gemm_qkv(QKVArgs args)
{
    extern __shared__ char smb[];
    const uint32_t sbase = smem_u32(smb);
    const int sel = blockIdx.z;
    const int bn = blockIdx.x * 128;
    const int bm = blockIdx.y * 128;
    const int lane = threadIdx.x & 31;
    const int wid = threadIdx.x >> 5;
    const int wm = wid & 1;
    const int wn = wid >> 1;

    float acc[4][4][4];
#pragma unroll
    for (int i = 0; i < 4; i++)
#pragma unroll
        for (int j = 0; j < 4; j++)
#pragma unroll
            for (int c = 0; c < 4; c++) acc[i][j][c] = 0.f;

    if (sel < 2) {
        mainloop_bf3(args.Ah[sel], args.Al[sel], args.Bh[sel], args.Bl[sel],
                     bm, bn, sbase, acc);
        const float* bias = args.bias[sel];
        __nv_bfloat16* Ch = args.Ch[sel];
        __nv_bfloat16* Cl = args.Cl[sel];
        // hoisted bias: 8 loads instead of 32
        float bia[4][2];
#pragma unroll
        for (int nt = 0; nt < 4; nt++) {
            const int n0 = bn + wn * 32 + nt * 8 + (lane & 3) * 2;
            bia[nt][0] = __ldg(&bias[n0]);
            bia[nt][1] = __ldg(&bias[n0 + 1]);
        }
#pragma unroll
        for (int mt = 0; mt < 4; mt++) {
#pragma unroll
            for (int nt = 0; nt < 4; nt++) {
                const int m0 = bm + wm * 64 + mt * 16 + (lane >> 2);
                const int n0 = bn + wn * 32 + nt * 8 + (lane & 3) * 2;
#pragma unroll
                for (int half = 0; half < 2; half++) {
                    const int m = m0 + half * 8;
                    const float x0 = acc[mt][nt][half * 2] + bia[nt][0];
                    const float x1 = acc[mt][nt][half * 2 + 1] + bia[nt][1];
                    const int h = bn >> 7;
                    const int b = m >> 11;
                    const int l = m & (LSEQ - 1);
                    const size_t idx =
                        (((size_t)(b * NH + h) * LSEQ + l) * DH) + (n0 & 127);
                    uint32_t hi, lo;
                    split2(x0, x1, hi, lo);
                    *(uint32_t*)(Ch + idx) = hi;
                    *(uint32_t*)(Cl + idx) = lo;
                }
            }
        }
    } else {
        mainloop_h1(args.vA, args.vB, bm, bn, sbase, acc);
        const float* bias = args.vbias;
        __half* C = args.vC;
        float bia[4][2];
#pragma unroll
        for (int nt = 0; nt < 4; nt++) {
            const int n0 = bn + wn * 32 + nt * 8 + (lane & 3) * 2;
            bia[nt][0] = __ldg(&bias[n0]);
            bia[nt][1] = __ldg(&bias[n0 + 1]);
        }
#pragma unroll
        for (int mt = 0; mt < 4; mt++) {
#pragma unroll
            for (int nt = 0; nt < 4; nt++) {
                const int m0 = bm + wm * 64 + mt * 16 + (lane >> 2);
                const int n0 = bn + wn * 32 + nt * 8 + (lane & 3) * 2;
#pragma unroll
                for (int half = 0; half < 2; half++) {
                    const int m = m0 + half * 8;
                    const int h = bn >> 7;
                    const int b = m >> 11;
                    const int l = m & (LSEQ - 1);
                    const size_t idx =
                        (((size_t)(b * NH + h) * LSEQ + l) * DH) + (n0 & 127);
                    *(uint32_t*)(C + idx) =
                        pack2h(acc[mt][nt][half * 2] + bia[nt][0],
                               acc[mt][nt][half * 2 + 1] + bia[nt][1]);
                }
            }
        }
    }
}

// ---------------------------------------------------------------------------
// Output projection — bias hoisted
// ---------------------------------------------------------------------------
__global__ __launch_bounds__(256)
void gemm_wo(const __half* __restrict__ A, const __half* __restrict__ B,
             const float* __restrict__ bias, float* __restrict__ C)
{
    extern __shared__ char smb[];
    const uint32_t sbase = smem_u32(smb);
    const int bn = blockIdx.x * 128;
    const int bm = blockIdx.y * 128;
    const int lane = threadIdx.x & 31;
    const int wid = threadIdx.x >> 5;
    const int wm = wid & 1;
    const int wn = wid >> 1;

    float acc[4][4][4];
#pragma unroll
    for (int i = 0; i < 4; i++)
#pragma unroll
        for (int j = 0; j < 4; j++)
#pragma unroll
            for (int c = 0; c < 4; c++) acc[i][j][c] = 0.f;

    mainloop_h1(A, B, bm, bn, sbase, acc);

    float bia[4][2];
#pragma unroll
    for (int nt = 0; nt < 4; nt++) {
        const int n0 = bn + wn * 32 + nt * 8 + (lane & 3) * 2;
        bia[nt][0] = __ldg(&bias[n0]);
        bia[nt][1] = __ldg(&bias[n0 + 1]);
    }
#pragma unroll
    for (int mt = 0; mt < 4; mt++) {
#pragma unroll
        for (int nt = 0; nt < 4; nt++) {
            const int m0 = bm + wm * 64 + mt * 16 + (lane >> 2);
            const int n0 = bn + wn * 32 + nt * 8 + (lane & 3) * 2;
#pragma unroll
            for (int half = 0; half < 2; half++) {
                const int m = m0 + half * 8;
                *(float2*)(C + (size_t)m * DMODEL + n0) =
                    make_float2(acc[mt][nt][half * 2] + bia[nt][0],
                                acc[mt][nt][half * 2 + 1] + bia[nt][1]);
            }
        }
    }
}

// ---------------------------------------------------------------------------
// Flash attention — round-14/15 version (tile-level causal skip, deferred l)
// ---------------------------------------------------------------------------
#define NQT (LSEQ / 128)
#define FST_B (3 * 64 * 256)                     // 48 KB
#define FQ_B  (2 * 128 * 256)                    // 64 KB
#define FSMEM_B (FQ_B + 3 * FST_B)               // 208 KB
#define FSCALE 11.31370849898476f

__global__ __launch_bounds__(256, 1)
void flash_mma(const __nv_bfloat16* __restrict__ Qhi,
               const __nv_bfloat16* __restrict__ Qlo,
               const __nv_bfloat16* __restrict__ Khi,
               const __nv_bfloat16* __restrict__ Klo,
               const __half* __restrict__ V,
               __half* __restrict__ O)
{
    extern __shared__ char smb[];
    const uint32_t sbase = smem_u32(smb);
    const uint32_t qlo_s = sbase + 128 * 256;
    const uint32_t stage0 = sbase + FQ_B;

    const int tid = threadIdx.x;
    const int lane = tid & 31;
    const int w = tid >> 5;

    const int bx = blockIdx.x;
    const int qt = (NQT - 1) - (bx >> 5);
    const int hb = bx & 31;
    const int h = hb & 15;
    const int b = hb >> 4;
    const int bh = b * NH + h;
    const int NKT = 2 * (qt + 1);

    const __nv_bfloat16* qh_g = Qhi + (size_t)bh * LSEQ * DH;
    const __nv_bfloat16* ql_g = Qlo + (size_t)bh * LSEQ * DH;
    const __nv_bfloat16* kh_g = Khi + (size_t)bh * LSEQ * DH;
    const __nv_bfloat16* kl_g = Klo + (size_t)bh * LSEQ * DH;
    const __half*        v_g  = V   + (size_t)bh * LSEQ * DH;

    {
#pragma unroll
        for (int j = 0; j < 16; j++) {
            const int c = tid + 256 * j;
            const int t = c >> 11;
            const int u = c & 2047;
            const int r = u >> 4;
            const int q = u & 15;
            const __nv_bfloat16* src = (t ? ql_g : qh_g) +
                (size_t)(qt * 128 + r) * DH + q * 8;
            cp16(sbase + (uint32_t)t * (128 * 256) + sw256(r, q), src);
        }
        CP_COMMIT();
    }

    auto load_stage = [&](int kt, int s) {
        const uint32_t st = stage0 + (uint32_t)s * FST_B;
#pragma unroll
        for (int j = 0; j < 12; j++) {
            const int c = tid + 256 * j;
            const int t = c >> 10;
            const int u = c & 1023;
            const int r = u >> 4;
            const int q = u & 15;
            const char* src =
                (t == 0 ? (const char*)kh_g :
                 t == 1 ? (const char*)kl_g : (const char*)v_g) +
                ((size_t)(kt * 64 + r) * DH + q * 8) * 2;
            cp16(st + (uint32_t)t * 16384 + sw256(r, q), src);
        }
        CP_COMMIT();
    };

    load_stage(0, 0);
    load_stage(1, 1);

    CP_WAIT(2);
    __syncthreads();

    uint32_t qfh[8][4];
#pragma unroll
    for (int ks = 0; ks < 8; ks++) {
        const int row = w * 16 + (lane & 15);
        const int q = ks * 2 + (lane >> 4);
        ldsm_x4(qfh[ks], sbase + sw256(row, q));
    }

    float O_acc[16][4];
#pragma unroll
    for (int nd = 0; nd < 16; nd++)
#pragma unroll
        for (int c = 0; c < 4; c++) O_acc[nd][c] = 0.f;
    float m0 = -3.0e38f, m1 = -3.0e38f, l0 = 0.f, l1 = 0.f;

    const int iq0 = qt * 128 + w * 16 + (lane >> 2);
    const int jcol = (lane & 3) * 2;
    const int rowmax = qt * 128 + w * 16 + 15;

    for (int kt = 0; kt < NKT; kt++) {
        if (kt + 1 < NKT) { CP_WAIT(1); } else { CP_WAIT(0); }
        __syncthreads();
        if (kt + 2 < NKT) load_stage(kt + 2, (kt + 2) % 3);

        const int colbase = kt * 64;
        if (colbase > rowmax) continue;

        const uint32_t st = stage0 + (uint32_t)(kt % 3) * FST_B;
        const uint32_t sKh = st;
        const uint32_t sKl = st + 16384;
        const uint32_t sV  = st + 32768;

        float S[8][4];
#pragma unroll
        for (int nt = 0; nt < 8; nt++)
#pragma unroll
            for (int c = 0; c < 4; c++) S[nt][c] = 0.f;

#pragma unroll
        for (int ks = 0; ks < 8; ks++) {
            uint32_t ql[4];
            {
                const int row = w * 16 + (lane & 15);
                const int q = ks * 2 + (lane >> 4);
                ldsm_x4(ql, qlo_s + sw256(row, q));
            }
            uint32_t kh4[4][4], kl4[4][4];
#pragma unroll
            for (int p = 0; p < 4; p++) {
                const int row = p * 16 + ((lane >> 4) & 1) * 8 + (lane & 7);
                const int q = ks * 2 + ((lane >> 3) & 1);
                ldsm_x4(kh4[p], sKh + sw256(row, q));
                ldsm_x4(kl4[p], sKl + sw256(row, q));
            }
#pragma unroll
            for (int nt = 0; nt < 8; nt++) {
                const uint32_t* kh = &kh4[nt >> 1][(nt & 1) * 2];
                const uint32_t* kl = &kl4[nt >> 1][(nt & 1) * 2];
                mma_bf16(S[nt], qfh[ks], kh);
                mma_bf16(S[nt], qfh[ks], kl);
                mma_bf16(S[nt], ql, kh);
            }
        }

        const bool tilemask = (colbase + 63) > (qt * 128 + w * 16);
#pragma unroll
        for (int nt = 0; nt < 8; nt++) {
#pragma unroll
            for (int c = 0; c < 4; c++) {
                float s = S[nt][c] * FSCALE;
                if (tilemask) {
                    const int i = iq0 + ((c & 2) ? 8 : 0);
                    const int j = colbase + nt * 8 + jcol + (c & 1);
                    if (j > i) s -= 1e7f;
                }
                S[nt][c] = s;
            }
        }

        float tm0 = -3.0e38f, tm1 = -3.0e38f;
#pragma unroll
        for (int nt = 0; nt < 8; nt++) {
            tm0 = fmaxf(tm0, fmaxf(S[nt][0], S[nt][1]));
            tm1 = fmaxf(tm1, fmaxf(S[nt][2], S[nt][3]));
        }
        tm0 = fmaxf(tm0, __shfl_xor_sync(0xffffffffu, tm0, 1));
        tm0 = fmaxf(tm0, __shfl_xor_sync(0xffffffffu, tm0, 2));
        tm1 = fmaxf(tm1, __shfl_xor_sync(0xffffffffu, tm1, 1));
        tm1 = fmaxf(tm1, __shfl_xor_sync(0xffffffffu, tm1, 2));
        const float nm0 = fmaxf(m0, tm0);
        const float nm1 = fmaxf(m1, tm1);

        const unsigned skip =
            __all_sync(0xffffffffu, (nm0 == m0) && (nm1 == m1));
        if (!skip) {
            const float a0 = __expf(m0 - nm0);
            const float a1 = __expf(m1 - nm1);
            l0 *= a0; l1 *= a1;
#pragma unroll
            for (int nd = 0; nd < 16; nd++) {
                O_acc[nd][0] *= a0; O_acc[nd][1] *= a0;
                O_acc[nd][2] *= a1; O_acc[nd][3] *= a1;
            }
            m0 = nm0; m1 = nm1;
        }

#pragma unroll
        for (int nt = 0; nt < 8; nt++) {
            S[nt][0] = __half2float(__float2half_rn(__expf(S[nt][0] - m0)));
            S[nt][1] = __half2float(__float2half_rn(__expf(S[nt][1] - m0)));
            S[nt][2] = __half2float(__float2half_rn(__expf(S[nt][2] - m1)));
            S[nt][3] = __half2float(__float2half_rn(__expf(S[nt][3] - m1)));
        }

#pragma unroll
        for (int ks2 = 0; ks2 < 4; ks2++) {
            const int nt0 = 2 * ks2, nt1 = nt0 + 1;
            uint32_t ph[4];
            ph[0] = pack2h(S[nt0][0], S[nt0][1]);
            ph[1] = pack2h(S[nt0][2], S[nt0][3]);
            ph[2] = pack2h(S[nt1][0], S[nt1][1]);
            ph[3] = pack2h(S[nt1][2], S[nt1][3]);
            const int vrow = ks2 * 16 + (lane & 15);
#pragma unroll
            for (int np = 0; np < 8; np++) {
                uint32_t vv[4];
                const int seg = np * 2 + (lane >> 4);
                ldsm_x4t(vv, sV + sw256(vrow, seg));
                mma_f16(O_acc[2 * np],     ph, vv);
                mma_f16(O_acc[2 * np + 1], ph, vv + 2);
            }
        }

        float s0 = 0.f, s1 = 0.f;
#pragma unroll
        for (int nt = 0; nt < 8; nt++) {
            s0 += S[nt][0] + S[nt][1];
            s1 += S[nt][2] + S[nt][3];
        }
        s0 += __shfl_xor_sync(0xffffffffu, s0, 1);
        s0 += __shfl_xor_sync(0xffffffffu, s0, 2);
        s1 += __shfl_xor_sync(0xffffffffu, s1, 1);
        s1 += __shfl_xor_sync(0xffffffffu, s1, 2);
        l0 += s0;
        l1 += s1;
    }

    const float inv0 = 1.0f / l0;
    const float inv1 = 1.0f / l1;
    const size_t tok0 = (size_t)b * LSEQ + qt * 128 + w * 16 + (lane >> 2);
    const size_t tok1 = tok0 + 8;
    const int col = h * DH + jcol;
#pragma unroll
    for (int nd = 0; nd < 16; nd++) {
        const int cc = col + nd * 8;
        *(uint32_t*)(O + tok0 * DMODEL + cc) =
            pack2h(O_acc[nd][0] * inv0, O_acc[nd][1] * inv0);
        *(uint32_t*)(O + tok1 * DMODEL + cc) =
            pack2h(O_acc[nd][2] * inv1, O_acc[nd][3] * inv1);
    }
}

// ---------------------------------------------------------------------------
extern "C" void kernel_launch(void* const* d_in, const int* in_sizes, int n_in,
                              void* d_out, int out_size)
{
    (void)in_sizes; (void)n_in; (void)out_size;
    const float* q  = (const float*)d_in[0];
    const float* k  = (const float*)d_in[1];
    const float* v  = (const float*)d_in[2];
    const float* Wq = (const float*)d_in[3];
    const float* bq = (const float*)d_in[4];
    const float* Wk = (const float*)d_in[5];
    const float* bk = (const float*)d_in[6];
    const float* Wv = (const float*)d_in[7];
    const float* bv = (const float*)d_in[8];
    const float* Wo = (const float*)d_in[9];
    const float* bo = (const float*)d_in[10];
    float* out = (float*)d_out;

    __nv_bfloat16 *sq, *sk, *qh2, *kh2, *swq, *swk;
    __half *sv, *sa, *vh2, *swv, *swo;
    cudaGetSymbolAddress((void**)&sq, g_sq);
    cudaGetSymbolAddress((void**)&sk, g_sk);
    cudaGetSymbolAddress((void**)&sv, g_sv);
    cudaGetSymbolAddress((void**)&sa, g_sa);
    cudaGetSymbolAddress((void**)&qh2, g_qh2);
    cudaGetSymbolAddress((void**)&kh2, g_kh2);
    cudaGetSymbolAddress((void**)&vh2, g_vh2);
    cudaGetSymbolAddress((void**)&swq, g_swq);
    cudaGetSymbolAddress((void**)&swk, g_swk);
    cudaGetSymbolAddress((void**)&swv, g_swv);
    cudaGetSymbolAddress((void**)&swo, g_swo);

    cudaFuncSetAttribute(gemm_qkv, cudaFuncAttributeMaxDynamicSharedMemorySize,
                         GS4_B);
    cudaFuncSetAttribute(gemm_wo, cudaFuncAttributeMaxDynamicSharedMemorySize,
                         GSH_B);
    cudaFuncSetAttribute(flash_mma, cudaFuncAttributeMaxDynamicSharedMemorySize,
                         FSMEM_B);

    // ---- prep (MLP 4) ----
    PrepArgs pa;
    pa.src[0] = q;  pa.dst[0] = sq;  pa.n[0] = (int)ACT_ELEMS; pa.type[0] = 0;
    pa.src[1] = k;  pa.dst[1] = sk;  pa.n[1] = (int)ACT_ELEMS; pa.type[1] = 0;
    pa.src[2] = v;  pa.dst[2] = sv;  pa.n[2] = (int)ACT_ELEMS; pa.type[2] = 2;
    pa.src[3] = Wq; pa.dst[3] = swq; pa.n[3] = (int)W_ELEMS;   pa.type[3] = 0;
    pa.src[4] = Wk; pa.dst[4] = swk; pa.n[4] = (int)W_ELEMS;   pa.type[4] = 0;
    pa.src[5] = Wv; pa.dst[5] = swv; pa.n[5] = (int)W_ELEMS;   pa.type[5] = 2;
    pa.src[6] = Wo; pa.dst[6] = swo; pa.n[6] = (int)W_ELEMS;   pa.type[6] = 2;
    for (int i = 0; i < 7; i++) pa.n4[i] = pa.n[i] / 4;
    prep<<<dim3((int)(ACT_ELEMS / 16 / 256), 1, 7), 256>>>(pa);

    // ---- fused Q/K/V projections ----
    QKVArgs qa;
    qa.Ah[0] = sq;  qa.Al[0] = sq + ACT_ELEMS;
    qa.Ah[1] = sk;  qa.Al[1] = sk + ACT_ELEMS;
    qa.Bh[0] = swq; qa.Bl[0] = swq + W_ELEMS;
    qa.Bh[1] = swk; qa.Bl[1] = swk + W_ELEMS;
    qa.bias[0] = bq; qa.bias[1] = bk;
    qa.Ch[0] = qh2; qa.Cl[0] = qh2 + ACT_ELEMS;
    qa.Ch[1] = kh2; qa.Cl[1] = kh2 + ACT_ELEMS;
    qa.vA = sv; qa.vB = swv; qa.vbias = bv; qa.vC = vh2;
    gemm_qkv<<<dim3(DMODEL / 128, MTOK / 128, 3), 256, GS4_B>>>(qa);

    // ---- attention ----
    flash_mma<<<NQT * NH * BATCH, 256, FSMEM_B>>>(
        qh2, qh2 + ACT_ELEMS, kh2, kh2 + ACT_ELEMS, vh2, sa);

    // ---- output projection ----
    gemm_wo<<<dim3(DMODEL / 128, MTOK / 128), 256, GSH_B>>>(sa, swo, bo, out);
}